// round 11
// baseline (speedup 1.0000x reference)
#include <cuda_runtime.h>
#include <cuda_bf16.h>
#include <math.h>
#include <stdint.h>

// Problem constants
#define NVOX 147456
#define CDIM 192
#define NH 8
#define DH 24
#define DFF 768
#define SETSZ 36
#define NSET 4096

// ---------------------------------------------------------------------------
// Scratch (device globals)
// ---------------------------------------------------------------------------
__device__ __nv_bfloat16 g_qk16[(size_t)NVOX * 2 * CDIM];  // Q|K voxel-order (stride 384)
__device__ __nv_bfloat16 g_qin16[(size_t)NVOX * CDIM];     // q_in (voxel) / attn out (set)
__device__ __nv_bfloat16 g_feat16[(size_t)NVOX * CDIM];    // bf16(cur), voxel order
__device__ __nv_bfloat16 g_v16[(size_t)NVOX * CDIM];       // V, voxel order
__device__ __nv_bfloat16 g_x16[(size_t)NVOX * CDIM];
__device__ __nv_bfloat16 g_h16[(size_t)NVOX * DFF];
__device__ float g_x32[(size_t)NVOX * CDIM];   // post-LN1 x (fp32)
// bf16 weights: [ipw | opw | l1w | l2w]
#define IPW_OFF 0
#define OPW_OFF 221184
#define L1W_OFF 294912
#define L2W_OFF 589824
#define W16_TOT 884736
__device__ __nv_bfloat16 g_w16[W16_TOT];

// ---------------------------------------------------------------------------
// mma.sync helpers
// ---------------------------------------------------------------------------
__device__ __forceinline__ void cp16(uint32_t dst, const void* src) {
    asm volatile("cp.async.cg.shared.global [%0], [%1], 16;\n" :: "r"(dst), "l"(src));
}
__device__ __forceinline__ void ldsm4(uint32_t* r, uint32_t addr) {
    asm volatile("ldmatrix.sync.aligned.m8n8.x4.shared.b16 {%0,%1,%2,%3}, [%4];"
                 : "=r"(r[0]), "=r"(r[1]), "=r"(r[2]), "=r"(r[3]) : "r"(addr));
}
__device__ __forceinline__ void mma_bf16(float* c, const uint32_t* a, const uint32_t* b) {
    asm volatile(
        "mma.sync.aligned.m16n8k16.row.col.f32.bf16.bf16.f32 "
        "{%0,%1,%2,%3},{%4,%5,%6,%7},{%8,%9},{%0,%1,%2,%3};"
        : "+f"(c[0]), "+f"(c[1]), "+f"(c[2]), "+f"(c[3])
        : "r"(a[0]), "r"(a[1]), "r"(a[2]), "r"(a[3]), "r"(b[0]), "r"(b[1]));
}
// Last chunk waits for its OWN group (wait_group 0); earlier leave prefetch in flight.
__device__ __forceinline__ void cp_wait(bool last) {
    if (last) asm volatile("cp.async.wait_group 0;" ::: "memory");
    else      asm volatile("cp.async.wait_group 1;" ::: "memory");
}
// Unpack 8 bf16 (uint4) -> two float4
__device__ __forceinline__ void unpack8_f4(uint4 u, float4& lo, float4& hi) {
    uint32_t w[4] = {u.x, u.y, u.z, u.w};
    float2 t0 = __bfloat1622float2(*reinterpret_cast<__nv_bfloat162*>(&w[0]));
    float2 t1 = __bfloat1622float2(*reinterpret_cast<__nv_bfloat162*>(&w[1]));
    float2 t2 = __bfloat1622float2(*reinterpret_cast<__nv_bfloat162*>(&w[2]));
    float2 t3 = __bfloat1622float2(*reinterpret_cast<__nv_bfloat162*>(&w[3]));
    lo = make_float4(t0.x, t0.y, t1.x, t1.y);
    hi = make_float4(t2.x, t2.y, t3.x, t3.y);
}

// ---------------------------------------------------------------------------
// Plain GEMM mainloop body (tile 256x64x32, 8 warps 4m x 2n, 3-stage).
// ---------------------------------------------------------------------------
#define GA_STAGE 16384
#define GB_STAGE 4096
#define GB_BASE  (3 * GA_STAGE)
#define GEMM_SMEM (3 * GA_STAGE + 3 * GB_STAGE)  // 61440

#define PLAIN_MAINLOOP(Aptr, Wptr, Kval)                                          \
    float acc[4][4][4];                                                           \
    _Pragma("unroll")                                                             \
    for (int mt = 0; mt < 4; mt++)                                                \
        _Pragma("unroll")                                                         \
        for (int nt = 0; nt < 4; nt++)                                            \
            _Pragma("unroll")                                                     \
            for (int r = 0; r < 4; r++) acc[mt][nt][r] = 0.f;                     \
    auto stage = [&](int kt, int buf) {                                           \
        const int k0 = kt * 32;                                                   \
        const uint32_t aB = sbase + buf * GA_STAGE;                               \
        const uint32_t bB = sbase + GB_BASE + buf * GB_STAGE;                     \
        _Pragma("unroll")                                                         \
        for (int i = 0; i < 4; i++) {                                             \
            int idx = i * 256 + tid;                                              \
            int row = idx >> 2, ch = idx & 3;                                     \
            cp16(aB + row * 64 + ((ch ^ ((row >> 1) & 3)) * 16),                  \
                 (Aptr) + (size_t)(m0 + row) * (Kval) + k0 + ch * 8);             \
        }                                                                         \
        {                                                                         \
            int row = tid >> 2, ch = tid & 3;                                     \
            cp16(bB + row * 64 + ((ch ^ ((row >> 1) & 3)) * 16),                  \
                 (Wptr) + (size_t)(n0 + row) * (Kval) + k0 + ch * 8);             \
        }                                                                         \
        asm volatile("cp.async.commit_group;" ::: "memory");                      \
    };                                                                            \
    const int nk = (Kval) >> 5;                                                   \
    stage(0, 0);                                                                  \
    stage(1, 1);                                                                  \
    for (int t = 0; t < nk; t++) {                                                \
        const int buf = t % 3;                                                    \
        cp_wait(t == nk - 1);                                                     \
        __syncthreads();                                                          \
        const uint32_t aB = sbase + buf * GA_STAGE;                               \
        const uint32_t bB = sbase + GB_BASE + buf * GB_STAGE;                     \
        _Pragma("unroll")                                                         \
        for (int ks = 0; ks < 2; ks++) {                                          \
            uint32_t af[4][4], bf[4][2];                                          \
            _Pragma("unroll")                                                     \
            for (int mt = 0; mt < 4; mt++) {                                      \
                int row = wm + mt * 16 + (lane & 15);                             \
                int ch = ks * 2 + (lane >> 4);                                    \
                ldsm4(af[mt], aB + row * 64 + ((ch ^ ((row >> 1) & 3)) * 16));    \
            }                                                                     \
            _Pragma("unroll")                                                     \
            for (int p = 0; p < 2; p++) {                                         \
                int row = wn + p * 16 + ((lane >> 4) << 3) + (lane & 7);          \
                int ch = ks * 2 + ((lane >> 3) & 1);                              \
                uint32_t r4[4];                                                   \
                ldsm4(r4, bB + row * 64 + ((ch ^ ((row >> 1) & 3)) * 16));        \
                bf[p * 2 + 0][0] = r4[0]; bf[p * 2 + 0][1] = r4[1];               \
                bf[p * 2 + 1][0] = r4[2]; bf[p * 2 + 1][1] = r4[3];               \
            }                                                                     \
            _Pragma("unroll")                                                     \
            for (int mt = 0; mt < 4; mt++)                                        \
                _Pragma("unroll")                                                 \
                for (int nt = 0; nt < 4; nt++)                                    \
                    mma_bf16(acc[mt][nt], af[mt], bf[nt]);                        \
        }                                                                         \
        __syncthreads();                                                          \
        if (t + 2 < nk) stage(t + 2, (t + 2) % 3);                                \
    }

// ---------------------------------------------------------------------------
// Plain bf16 GEMM (lin1): D[M,Nc] = A @ W^T + bias (opt ReLU)
// ---------------------------------------------------------------------------
template <typename OutT, bool RELU>
__global__ __launch_bounds__(256) void gemm_bf16_kernel(
        const __nv_bfloat16* __restrict__ A,
        const __nv_bfloat16* __restrict__ W,
        const float* __restrict__ bias,
        OutT* __restrict__ D,
        int K, int Nc) {
    extern __shared__ unsigned char smem[];
    const uint32_t sbase = (uint32_t)__cvta_generic_to_shared(smem);
    const int tid = threadIdx.x;
    const int lane = tid & 31;
    const int wid = tid >> 5;
    const int wm = (wid & 3) * 64;
    const int wn = (wid >> 2) * 32;
    const int m0 = blockIdx.y * 256;
    const int n0 = blockIdx.x * 64;

    PLAIN_MAINLOOP(A, W, K)

#pragma unroll
    for (int mt = 0; mt < 4; mt++) {
#pragma unroll
        for (int nt = 0; nt < 4; nt++) {
            int m = m0 + wm + mt * 16 + (lane >> 2);
            int n = n0 + wn + nt * 8 + (lane & 3) * 2;
            float b0 = bias[n], b1 = bias[n + 1];
            float v0 = acc[mt][nt][0] + b0;
            float v1 = acc[mt][nt][1] + b1;
            float v2 = acc[mt][nt][2] + b0;
            float v3 = acc[mt][nt][3] + b1;
            if (RELU) {
                v0 = fmaxf(v0, 0.f); v1 = fmaxf(v1, 0.f);
                v2 = fmaxf(v2, 0.f); v3 = fmaxf(v3, 0.f);
            }
            if constexpr (sizeof(OutT) == 2) {
                *reinterpret_cast<__nv_bfloat162*>((__nv_bfloat16*)D + (size_t)m * Nc + n) =
                    __floats2bfloat162_rn(v0, v1);
                *reinterpret_cast<__nv_bfloat162*>((__nv_bfloat16*)D + (size_t)(m + 8) * Nc + n) =
                    __floats2bfloat162_rn(v2, v3);
            } else {
                *reinterpret_cast<float2*>((float*)D + (size_t)m * Nc + n) = make_float2(v0, v1);
                *reinterpret_cast<float2*>((float*)D + (size_t)(m + 8) * Nc + n) = make_float2(v2, v3);
            }
        }
    }
}

// ---------------------------------------------------------------------------
// Merged QKV GEMM: Nc spans 576 (Wq|Wk|Wv rows contiguous).
// ---------------------------------------------------------------------------
__global__ __launch_bounds__(256) void qkv_gemm_kernel(
        const __nv_bfloat16* __restrict__ Aq,
        const __nv_bfloat16* __restrict__ Af,
        const __nv_bfloat16* __restrict__ W,
        const float* __restrict__ bias,
        __nv_bfloat16* __restrict__ Dqk,
        __nv_bfloat16* __restrict__ Dv) {
    extern __shared__ unsigned char smem[];
    const uint32_t sbase = (uint32_t)__cvta_generic_to_shared(smem);
    const int tid = threadIdx.x;
    const int lane = tid & 31;
    const int wid = tid >> 5;
    const int wm = (wid & 3) * 64;
    const int wn = (wid >> 2) * 32;
    const int m0 = blockIdx.y * 256;
    const int n0 = blockIdx.x * 64;

    const bool isV = (n0 >= 2 * CDIM);
    const __nv_bfloat16* A = isV ? Af : Aq;
    __nv_bfloat16* D = isV ? Dv : Dqk;
    const int dStride = isV ? CDIM : 2 * CDIM;
    const int dCol0 = isV ? n0 - 2 * CDIM : n0;

    PLAIN_MAINLOOP(A, W, CDIM)

#pragma unroll
    for (int mt = 0; mt < 4; mt++) {
#pragma unroll
        for (int nt = 0; nt < 4; nt++) {
            int m = m0 + wm + mt * 16 + (lane >> 2);
            int nl = wn + nt * 8 + (lane & 3) * 2;
            int n = n0 + nl;
            float b0 = bias[n], b1 = bias[n + 1];
            int nd = dCol0 + nl;
            *reinterpret_cast<__nv_bfloat162*>(D + (size_t)m * dStride + nd) =
                __floats2bfloat162_rn(acc[mt][nt][0] + b0, acc[mt][nt][1] + b1);
            *reinterpret_cast<__nv_bfloat162*>(D + (size_t)(m + 8) * dStride + nd) =
                __floats2bfloat162_rn(acc[mt][nt][2] + b0, acc[mt][nt][3] + b1);
        }
    }
}

// ---------------------------------------------------------------------------
// Fused GEMM mainloop config (tile 64 x 192, K chunks of 32, 3-stage).
// ---------------------------------------------------------------------------
#define FA_STAGE 4096
#define FB_STAGE 12288
#define FB_BASE  (3 * FA_STAGE)
#define FUSED_SMEM (3 * FA_STAGE + 3 * FB_STAGE)  // 49152

#define FUSED_MAINLOOP(Aptr, Wptr, Kval)                                              \
    float acc[2][6][4];                                                               \
    _Pragma("unroll")                                                                 \
    for (int mt = 0; mt < 2; mt++)                                                    \
        _Pragma("unroll")                                                             \
        for (int nt = 0; nt < 6; nt++)                                                \
            _Pragma("unroll")                                                         \
            for (int r = 0; r < 4; r++) acc[mt][nt][r] = 0.f;                         \
    auto stage = [&](int kt, int buf) {                                               \
        const int k0 = kt * 32;                                                       \
        {                                                                             \
            int row = tid >> 2, ch = tid & 3;                                         \
            cp16(sbase + buf * FA_STAGE + row * 64 + ((ch ^ ((row >> 1) & 3)) * 16),  \
                 (Aptr) + (size_t)(m0 + row) * (Kval) + k0 + ch * 8);                 \
        }                                                                             \
        _Pragma("unroll")                                                             \
        for (int i = 0; i < 3; i++) {                                                 \
            int idx = i * 256 + tid;                                                  \
            int row = idx >> 2, ch = idx & 3;                                         \
            cp16(sbase + FB_BASE + buf * FB_STAGE + row * 64 +                        \
                     ((ch ^ ((row >> 1) & 3)) * 16),                                  \
                 (Wptr) + (size_t)row * (Kval) + k0 + ch * 8);                        \
        }                                                                             \
        asm volatile("cp.async.commit_group;" ::: "memory");                          \
    };                                                                                \
    const int nk = (Kval) >> 5;                                                       \
    stage(0, 0);                                                                      \
    stage(1, 1);                                                                      \
    for (int t = 0; t < nk; t++) {                                                    \
        const int buf = t % 3;                                                        \
        cp_wait(t == nk - 1);                                                         \
        __syncthreads();                                                              \
        const uint32_t aB = sbase + buf * FA_STAGE;                                   \
        const uint32_t bB = sbase + FB_BASE + buf * FB_STAGE;                         \
        _Pragma("unroll")                                                             \
        for (int ks = 0; ks < 2; ks++) {                                              \
            uint32_t af[2][4], bf[6][2];                                              \
            _Pragma("unroll")                                                         \
            for (int mt = 0; mt < 2; mt++) {                                          \
                int row = wm + mt * 16 + (lane & 15);                                 \
                int ch = ks * 2 + (lane >> 4);                                        \
                ldsm4(af[mt], aB + row * 64 + ((ch ^ ((row >> 1) & 3)) * 16));        \
            }                                                                         \
            _Pragma("unroll")                                                         \
            for (int p = 0; p < 3; p++) {                                             \
                int row = wn + p * 16 + ((lane >> 4) << 3) + (lane & 7);              \
                int ch = ks * 2 + ((lane >> 3) & 1);                                  \
                uint32_t r4[4];                                                       \
                ldsm4(r4, bB + row * 64 + ((ch ^ ((row >> 1) & 3)) * 16));            \
                bf[p * 2 + 0][0] = r4[0]; bf[p * 2 + 0][1] = r4[1];                   \
                bf[p * 2 + 1][0] = r4[2]; bf[p * 2 + 1][1] = r4[3];                   \
            }                                                                         \
            _Pragma("unroll")                                                         \
            for (int mt = 0; mt < 2; mt++)                                            \
                _Pragma("unroll")                                                     \
                for (int nt = 0; nt < 6; nt++)                                        \
                    mma_bf16(acc[mt][nt], af[mt], bf[nt]);                            \
        }                                                                             \
        __syncthreads();                                                              \
        if (t + 2 < nk) stage(t + 2, (t + 2) % 3);                                    \
    }

// ---------------------------------------------------------------------------
// Fused out_proj + scatter + residual + LN1.
// ---------------------------------------------------------------------------
__global__ __launch_bounds__(256) void gemm_op_ln1_kernel(
        const __nv_bfloat16* __restrict__ A,
        const __nv_bfloat16* __restrict__ W,
        const float* __restrict__ bias,
        const float* __restrict__ cur,
        const int* __restrict__ inds_all, const int* __restrict__ block_id, int layer,
        const float* __restrict__ lnw, const float* __restrict__ lnb,
        float* __restrict__ x32, __nv_bfloat16* __restrict__ x16) {
    extern __shared__ unsigned char smem[];
    const uint32_t sbase = (uint32_t)__cvta_generic_to_shared(smem);
    const int tid = threadIdx.x;
    const int lane = tid & 31;
    const int wid = tid >> 5;
    const int wm = (wid & 1) * 32;
    const int wn = (wid >> 1) * 48;
    const int m0 = blockIdx.x * 64;

    FUSED_MAINLOOP(A, W, CDIM)

    float* stats = reinterpret_cast<float*>(smem);
    const int gid = lane >> 2, tig = lane & 3;
    const int shift = block_id[0] & 1;
    const int* ip = inds_all + ((size_t)shift * 2 + layer) * NVOX;
    int vrow[2][2];
#pragma unroll
    for (int mt = 0; mt < 2; mt++) {
#pragma unroll
        for (int mm = 0; mm < 2; mm++) {
            int rloc = wm + mt * 16 + mm * 8 + gid;
            int v = ip[m0 + rloc];
            vrow[mt][mm] = v;
            float s = 0.f, s2 = 0.f;
#pragma unroll
            for (int nt = 0; nt < 6; nt++) {
                int n = wn + nt * 8 + tig * 2;
                float2 c = *reinterpret_cast<const float2*>(cur + (size_t)v * CDIM + n);
                float a0 = acc[mt][nt][mm * 2]     + bias[n]     + c.x;
                float a1 = acc[mt][nt][mm * 2 + 1] + bias[n + 1] + c.y;
                acc[mt][nt][mm * 2] = a0; acc[mt][nt][mm * 2 + 1] = a1;
                s += a0 + a1; s2 += a0 * a0 + a1 * a1;
            }
            s  += __shfl_xor_sync(0xffffffffu, s, 1);  s  += __shfl_xor_sync(0xffffffffu, s, 2);
            s2 += __shfl_xor_sync(0xffffffffu, s2, 1); s2 += __shfl_xor_sync(0xffffffffu, s2, 2);
            if (tig == 0) {
                stats[((wid >> 1) * 64 + rloc) * 2]     = s;
                stats[((wid >> 1) * 64 + rloc) * 2 + 1] = s2;
            }
        }
    }
    __syncthreads();
#pragma unroll
    for (int mt = 0; mt < 2; mt++) {
#pragma unroll
        for (int mm = 0; mm < 2; mm++) {
            int rloc = wm + mt * 16 + mm * 8 + gid;
            int v = vrow[mt][mm];
            float S = 0.f, S2 = 0.f;
#pragma unroll
            for (int g = 0; g < 4; g++) {
                S  += stats[(g * 64 + rloc) * 2];
                S2 += stats[(g * 64 + rloc) * 2 + 1];
            }
            float mean = S * (1.0f / CDIM);
            float var = S2 * (1.0f / CDIM) - mean * mean;
            float rs = rsqrtf(var + 1e-5f);
#pragma unroll
            for (int nt = 0; nt < 6; nt++) {
                int n = wn + nt * 8 + tig * 2;
                float o0 = (acc[mt][nt][mm * 2]     - mean) * rs * lnw[n]     + lnb[n];
                float o1 = (acc[mt][nt][mm * 2 + 1] - mean) * rs * lnw[n + 1] + lnb[n + 1];
                *reinterpret_cast<float2*>(x32 + (size_t)v * CDIM + n) = make_float2(o0, o1);
                *reinterpret_cast<__nv_bfloat162*>(x16 + (size_t)v * CDIM + n) =
                    __floats2bfloat162_rn(o0, o1);
            }
        }
    }
}

// ---------------------------------------------------------------------------
// Fused lin2 + LN2 + LN3 (voxel-order rows).
// ---------------------------------------------------------------------------
__global__ __launch_bounds__(256) void gemm_ffn_ln23_kernel(
        const __nv_bfloat16* __restrict__ A,
        const __nv_bfloat16* __restrict__ W,
        const float* __restrict__ bias,
        const float* __restrict__ x32,
        const float* __restrict__ cur,
        const float* __restrict__ w2, const float* __restrict__ b2,
        const float* __restrict__ w3, const float* __restrict__ b3,
        float* __restrict__ outp) {
    extern __shared__ unsigned char smem[];
    const uint32_t sbase = (uint32_t)__cvta_generic_to_shared(smem);
    const int tid = threadIdx.x;
    const int lane = tid & 31;
    const int wid = tid >> 5;
    const int wm = (wid & 1) * 32;
    const int wn = (wid >> 1) * 48;
    const int m0 = blockIdx.x * 64;

    FUSED_MAINLOOP(A, W, DFF)

    float* stats = reinterpret_cast<float*>(smem);
    const int gid = lane >> 2, tig = lane & 3;

#pragma unroll
    for (int mt = 0; mt < 2; mt++) {
#pragma unroll
        for (int mm = 0; mm < 2; mm++) {
            int rloc = wm + mt * 16 + mm * 8 + gid;
            int v = m0 + rloc;
            float s = 0.f, s2 = 0.f;
#pragma unroll
            for (int nt = 0; nt < 6; nt++) {
                int n = wn + nt * 8 + tig * 2;
                float2 xr = *reinterpret_cast<const float2*>(x32 + (size_t)v * CDIM + n);
                float a0 = acc[mt][nt][mm * 2]     + bias[n]     + xr.x;
                float a1 = acc[mt][nt][mm * 2 + 1] + bias[n + 1] + xr.y;
                acc[mt][nt][mm * 2] = a0; acc[mt][nt][mm * 2 + 1] = a1;
                s += a0 + a1; s2 += a0 * a0 + a1 * a1;
            }
            s  += __shfl_xor_sync(0xffffffffu, s, 1);  s  += __shfl_xor_sync(0xffffffffu, s, 2);
            s2 += __shfl_xor_sync(0xffffffffu, s2, 1); s2 += __shfl_xor_sync(0xffffffffu, s2, 2);
            if (tig == 0) {
                stats[((wid >> 1) * 64 + rloc) * 2]     = s;
                stats[((wid >> 1) * 64 + rloc) * 2 + 1] = s2;
            }
        }
    }
    __syncthreads();

    float sB[2][2], s2B[2][2];
#pragma unroll
    for (int mt = 0; mt < 2; mt++) {
#pragma unroll
        for (int mm = 0; mm < 2; mm++) {
            int rloc = wm + mt * 16 + mm * 8 + gid;
            int v = m0 + rloc;
            float S = 0.f, S2 = 0.f;
#pragma unroll
            for (int g = 0; g < 4; g++) {
                S  += stats[(g * 64 + rloc) * 2];
                S2 += stats[(g * 64 + rloc) * 2 + 1];
            }
            float mean = S * (1.0f / CDIM);
            float var = S2 * (1.0f / CDIM) - mean * mean;
            float rs = rsqrtf(var + 1e-5f);
            float s = 0.f, s2 = 0.f;
#pragma unroll
            for (int nt = 0; nt < 6; nt++) {
                int n = wn + nt * 8 + tig * 2;
                float2 cv = *reinterpret_cast<const float2*>(cur + (size_t)v * CDIM + n);
                float t0 = (acc[mt][nt][mm * 2]     - mean) * rs * w2[n]     + b2[n]     + cv.x;
                float t1 = (acc[mt][nt][mm * 2 + 1] - mean) * rs * w2[n + 1] + b2[n + 1] + cv.y;
                acc[mt][nt][mm * 2] = t0; acc[mt][nt][mm * 2 + 1] = t1;
                s += t0 + t1; s2 += t0 * t0 + t1 * t1;
            }
            s  += __shfl_xor_sync(0xffffffffu, s, 1);  s  += __shfl_xor_sync(0xffffffffu, s, 2);
            s2 += __shfl_xor_sync(0xffffffffu, s2, 1); s2 += __shfl_xor_sync(0xffffffffu, s2, 2);
            sB[mt][mm] = s; s2B[mt][mm] = s2;
        }
    }
    __syncthreads();
#pragma unroll
    for (int mt = 0; mt < 2; mt++)
#pragma unroll
        for (int mm = 0; mm < 2; mm++) {
            int rloc = wm + mt * 16 + mm * 8 + gid;
            if (tig == 0) {
                stats[((wid >> 1) * 64 + rloc) * 2]     = sB[mt][mm];
                stats[((wid >> 1) * 64 + rloc) * 2 + 1] = s2B[mt][mm];
            }
        }
    __syncthreads();

#pragma unroll
    for (int mt = 0; mt < 2; mt++) {
#pragma unroll
        for (int mm = 0; mm < 2; mm++) {
            int rloc = wm + mt * 16 + mm * 8 + gid;
            int v = m0 + rloc;
            float S = 0.f, S2 = 0.f;
#pragma unroll
            for (int g = 0; g < 4; g++) {
                S  += stats[(g * 64 + rloc) * 2];
                S2 += stats[(g * 64 + rloc) * 2 + 1];
            }
            float mean = S * (1.0f / CDIM);
            float var = S2 * (1.0f / CDIM) - mean * mean;
            float rs = rsqrtf(var + 1e-5f);
#pragma unroll
            for (int nt = 0; nt < 6; nt++) {
                int n = wn + nt * 8 + tig * 2;
                float o0 = (acc[mt][nt][mm * 2]     - mean) * rs * w3[n]     + b3[n];
                float o1 = (acc[mt][nt][mm * 2 + 1] - mean) * rs * w3[n + 1] + b3[n + 1];
                *reinterpret_cast<float2*>(outp + (size_t)v * CDIM + n) = make_float2(o0, o1);
            }
        }
    }
}

// ---------------------------------------------------------------------------
// Single merged weight converter
// ---------------------------------------------------------------------------
__global__ void cvt_all_kernel(const float* __restrict__ ipw,
                               const float* __restrict__ opw,
                               const float* __restrict__ l1w,
                               const float* __restrict__ l2w,
                               __nv_bfloat16* __restrict__ dst) {
    int i = blockIdx.x * blockDim.x + threadIdx.x;
    const int N4 = W16_TOT / 4;
    if (i >= N4) return;
    int e = i * 4;
    const float* src;
    int off;
    if (e < OPW_OFF)      { src = ipw; off = e - IPW_OFF; }
    else if (e < L1W_OFF) { src = opw; off = e - OPW_OFF; }
    else if (e < L2W_OFF) { src = l1w; off = e - L1W_OFF; }
    else                  { src = l2w; off = e - L2W_OFF; }
    float4 v = *reinterpret_cast<const float4*>(src + off);
    reinterpret_cast<__nv_bfloat162*>(dst)[i * 2 + 0] = __floats2bfloat162_rn(v.x, v.y);
    reinterpret_cast<__nv_bfloat162*>(dst)[i * 2 + 1] = __floats2bfloat162_rn(v.z, v.w);
}

// ---------------------------------------------------------------------------
// Prep (coalesced, voxel order): qin16 = bf16(cur+pos); feat16 = bf16(cur)
// ---------------------------------------------------------------------------
__global__ void prep_kernel(const float* __restrict__ cur,
                            const float* __restrict__ pos,
                            __nv_bfloat16* __restrict__ qin,
                            __nv_bfloat16* __restrict__ feat) {
    int gid = blockIdx.x * blockDim.x + threadIdx.x;
    const int TOT = NVOX * (CDIM / 4);
    if (gid >= TOT) return;
    float4 f = reinterpret_cast<const float4*>(cur)[gid];
    float4 pp = reinterpret_cast<const float4*>(pos)[gid];
    __nv_bfloat162* f2 = reinterpret_cast<__nv_bfloat162*>(feat);
    __nv_bfloat162* q2 = reinterpret_cast<__nv_bfloat162*>(qin);
    f2[gid * 2 + 0] = __floats2bfloat162_rn(f.x, f.y);
    f2[gid * 2 + 1] = __floats2bfloat162_rn(f.z, f.w);
    q2[gid * 2 + 0] = __floats2bfloat162_rn(f.x + pp.x, f.y + pp.y);
    q2[gid * 2 + 1] = __floats2bfloat162_rn(f.z + pp.z, f.w + pp.w);
}

// ---------------------------------------------------------------------------
// Attention: one block per set, 288 threads = (36 rows x 8 heads).
// Q/K/V staged in smem as FP32 (unpacked once, cooperatively, at fill time).
// Inner loops: pure LDS.128 fp32 (broadcast) + FFMA, no per-thread cvt.
// Dynamic smem: 3 * 36 * 192 * 4 = 82944 B.
// ---------------------------------------------------------------------------
#define ATTN_SMEM (3 * SETSZ * CDIM * 4 + 160)

__global__ __launch_bounds__(288) void attn_kernel(const __nv_bfloat16* __restrict__ qk,
                                                   const __nv_bfloat16* __restrict__ v,
                                                   const int* __restrict__ inds_all,
                                                   const int* __restrict__ block_id,
                                                   int layer,
                                                   __nv_bfloat16* __restrict__ o) {
    extern __shared__ float smf[];
    float* qs = smf;                      // 36 x 192
    float* ks = smf + SETSZ * CDIM;       // 36 x 192
    float* vs = smf + 2 * SETSZ * CDIM;   // 36 x 192
    int* vids = reinterpret_cast<int*>(smf + 3 * SETSZ * CDIM);

    int s = blockIdx.x;
    int tid = threadIdx.x;

    if (tid < SETSZ) {
        int shift = block_id[0] & 1;
        vids[tid] = inds_all[((size_t)shift * 2 + layer) * NVOX + s * SETSZ + tid];
    }
    __syncthreads();

    // Fill Q/K (from qk rows: 48 uint4 each = q cols [0,24) | k cols [24,48))
    const uint4* qk4 = reinterpret_cast<const uint4*>(qk);
    const uint4* v4 = reinterpret_cast<const uint4*>(v);
    for (int idx = tid; idx < SETSZ * 48; idx += 288) {
        int row = idx / 48, c = idx % 48;
        uint4 u = qk4[(size_t)vids[row] * 48 + c];
        float4 lo, hi;
        unpack8_f4(u, lo, hi);
        float* dst = (c < 24) ? (qs + row * CDIM + c * 8)
                              : (ks + row * CDIM + (c - 24) * 8);
        reinterpret_cast<float4*>(dst)[0] = lo;
        reinterpret_cast<float4*>(dst)[1] = hi;
    }
    // Fill V (24 uint4 per row)
    for (int idx = tid; idx < SETSZ * 24; idx += 288) {
        int row = idx / 24, c = idx % 24;
        uint4 u = v4[(size_t)vids[row] * 24 + c];
        float4 lo, hi;
        unpack8_f4(u, lo, hi);
        float* dst = vs + row * CDIM + c * 8;
        reinterpret_cast<float4*>(dst)[0] = lo;
        reinterpret_cast<float4*>(dst)[1] = hi;
    }
    __syncthreads();

    int l = tid % SETSZ;
    int h = tid / SETSZ;

    // q row: 24 floats = 6 float4
    float qr[DH];
    {
        const float4* qrow = reinterpret_cast<const float4*>(qs + l * CDIM + h * DH);
#pragma unroll
        for (int c = 0; c < 6; c++) {
            float4 t = qrow[c];
            qr[c * 4 + 0] = t.x; qr[c * 4 + 1] = t.y;
            qr[c * 4 + 2] = t.z; qr[c * 4 + 3] = t.w;
        }
    }

    const float scale = 0.20412414523193154f;
    float sc[SETSZ];
    float mx = -1e30f;
#pragma unroll 4
    for (int m = 0; m < SETSZ; m++) {
        const float4* krow = reinterpret_cast<const float4*>(ks + m * CDIM + h * DH);
        float dot = 0.f;
#pragma unroll
        for (int c = 0; c < 6; c++) {
            float4 t = krow[c];
            dot += qr[c * 4 + 0] * t.x + qr[c * 4 + 1] * t.y
                 + qr[c * 4 + 2] * t.z + qr[c * 4 + 3] * t.w;
        }
        dot *= scale;
        sc[m] = dot;
        mx = fmaxf(mx, dot);
    }
    float sum = 0.f;
#pragma unroll 4
    for (int m = 0; m < SETSZ; m++) {
        sc[m] = expf(sc[m] - mx);
        sum += sc[m];
    }
    float inv = 1.0f / sum;

    // attn @ V
    float acc[DH];
#pragma unroll
    for (int d = 0; d < DH; d++) acc[d] = 0.f;
#pragma unroll 4
    for (int m = 0; m < SETSZ; m++) {
        const float4* vrow = reinterpret_cast<const float4*>(vs + m * CDIM + h * DH);
        float p = sc[m];
#pragma unroll
        for (int c = 0; c < 6; c++) {
            float4 t = vrow[c];
            acc[c * 4 + 0] += p * t.x; acc[c * 4 + 1] += p * t.y;
            acc[c * 4 + 2] += p * t.z; acc[c * 4 + 3] += p * t.w;
        }
    }

    __nv_bfloat162* o2 = reinterpret_cast<__nv_bfloat162*>(
        o + (size_t)s * SETSZ * CDIM + l * CDIM + h * DH);
#pragma unroll
    for (int d2 = 0; d2 < DH / 2; d2++)
        o2[d2] = __floats2bfloat162_rn(acc[d2 * 2] * inv, acc[d2 * 2 + 1] * inv);
}

// ---------------------------------------------------------------------------
// Host orchestration
// ---------------------------------------------------------------------------
extern "C" void kernel_launch(void* const* d_in, const int* in_sizes, int n_in,
                              void* d_out, int out_size) {
    (void)in_sizes; (void)n_in; (void)out_size;
    const float* src  = (const float*)d_in[0];
    const int*   inds = (const int*)d_in[1];
    const float* pos  = (const float*)d_in[3];
    const int*   bid  = (const int*)d_in[4];
    const float* ipw  = (const float*)d_in[5];
    const float* ipb  = (const float*)d_in[6];
    const float* opw  = (const float*)d_in[7];
    const float* opb  = (const float*)d_in[8];
    const float* l1w  = (const float*)d_in[9];
    const float* l1b  = (const float*)d_in[10];
    const float* l2w  = (const float*)d_in[11];
    const float* l2b  = (const float*)d_in[12];
    const float* n1w  = (const float*)d_in[13];
    const float* n1b  = (const float*)d_in[14];
    const float* n2w  = (const float*)d_in[15];
    const float* n2b  = (const float*)d_in[16];
    const float* n3w  = (const float*)d_in[17];
    const float* n3b  = (const float*)d_in[18];

    float* out = (float*)d_out;

    __nv_bfloat16 *qk16, *qin16, *feat16, *v16, *x16, *h16, *w16;
    float *x32;
    cudaGetSymbolAddress((void**)&qk16, g_qk16);
    cudaGetSymbolAddress((void**)&qin16, g_qin16);
    cudaGetSymbolAddress((void**)&feat16, g_feat16);
    cudaGetSymbolAddress((void**)&v16, g_v16);
    cudaGetSymbolAddress((void**)&x16, g_x16);
    cudaGetSymbolAddress((void**)&h16, g_h16);
    cudaGetSymbolAddress((void**)&w16, g_w16);
    cudaGetSymbolAddress((void**)&x32, g_x32);

    cudaFuncSetAttribute((const void*)gemm_bf16_kernel<__nv_bfloat16, true>,
                         cudaFuncAttributeMaxDynamicSharedMemorySize, GEMM_SMEM);
    cudaFuncSetAttribute((const void*)qkv_gemm_kernel,
                         cudaFuncAttributeMaxDynamicSharedMemorySize, GEMM_SMEM);
    cudaFuncSetAttribute((const void*)gemm_op_ln1_kernel,
                         cudaFuncAttributeMaxDynamicSharedMemorySize, FUSED_SMEM);
    cudaFuncSetAttribute((const void*)gemm_ffn_ln23_kernel,
                         cudaFuncAttributeMaxDynamicSharedMemorySize, FUSED_SMEM);
    cudaFuncSetAttribute((const void*)attn_kernel,
                         cudaFuncAttributeMaxDynamicSharedMemorySize, ATTN_SMEM);

    cvt_all_kernel<<<(W16_TOT / 4 + 255) / 256, 256>>>(ipw, opw, l1w, l2w, w16);

    const int TOT4 = NVOX * (CDIM / 4);
    dim3 pgrid((TOT4 + 255) / 256);
    dim3 gridQKV(9, NVOX / 256);
    dim3 grid768(DFF / 64, NVOX / 256);
    dim3 fgrid(NVOX / 64);

    for (int i = 0; i < 2; i++) {
        const __nv_bfloat16* Wqkv = w16 + IPW_OFF + (size_t)i * 3 * CDIM * CDIM;
        const float* bqkv = ipb + (size_t)i * 3 * CDIM;
        const float* posL = pos + (size_t)i * NVOX * CDIM;
        const float* cur = (i == 0) ? src : out;

        prep_kernel<<<pgrid, 256>>>(cur, posL, qin16, feat16);

        qkv_gemm_kernel<<<gridQKV, 256, GEMM_SMEM>>>(
            qin16, feat16, Wqkv, bqkv, qk16, v16);

        attn_kernel<<<NSET, 288, ATTN_SMEM>>>(qk16, v16, inds, bid, i, qin16);

        gemm_op_ln1_kernel<<<fgrid, 256, FUSED_SMEM>>>(
            qin16, w16 + OPW_OFF + (size_t)i * CDIM * CDIM, opb + (size_t)i * CDIM,
            cur, inds, bid, i, n1w + i * CDIM, n1b + i * CDIM, x32, x16);

        gemm_bf16_kernel<__nv_bfloat16, true><<<grid768, 256, GEMM_SMEM>>>(
            x16, w16 + L1W_OFF + (size_t)i * DFF * CDIM, l1b + (size_t)i * DFF,
            h16, CDIM, DFF);

        gemm_ffn_ln23_kernel<<<fgrid, 256, FUSED_SMEM>>>(
            h16, w16 + L2W_OFF + (size_t)i * CDIM * DFF, l2b + (size_t)i * CDIM,
            x32, cur, n2w + i * CDIM, n2b + i * CDIM,
            n3w + i * CDIM, n3b + i * CDIM, out);
    }
}

// round 12
// speedup vs baseline: 1.0614x; 1.0614x over previous
#include <cuda_runtime.h>
#include <cuda_bf16.h>
#include <math.h>
#include <stdint.h>

// Problem constants
#define NVOX 147456
#define CDIM 192
#define NH 8
#define DH 24
#define DFF 768
#define SETSZ 36
#define NSET 4096

// ---------------------------------------------------------------------------
// Scratch (device globals)
// ---------------------------------------------------------------------------
__device__ __nv_bfloat16 g_qk16[(size_t)NVOX * 2 * CDIM];  // Q|K voxel-order (stride 384)
__device__ __nv_bfloat16 g_qin16[(size_t)NVOX * CDIM];     // q_in (voxel) / attn out (set)
__device__ __nv_bfloat16 g_feat16[(size_t)NVOX * CDIM];    // bf16(cur), voxel order
__device__ __nv_bfloat16 g_v16[(size_t)NVOX * CDIM];       // V, voxel order
__device__ __nv_bfloat16 g_x16[(size_t)NVOX * CDIM];
__device__ __nv_bfloat16 g_h16[(size_t)NVOX * DFF];
__device__ float g_x32[(size_t)NVOX * CDIM];   // post-LN1 x (fp32)
// bf16 weights: [ipw | opw | l1w | l2w]
#define IPW_OFF 0
#define OPW_OFF 221184
#define L1W_OFF 294912
#define L2W_OFF 589824
#define W16_TOT 884736
__device__ __nv_bfloat16 g_w16[W16_TOT];

// ---------------------------------------------------------------------------
// mma.sync helpers
// ---------------------------------------------------------------------------
__device__ __forceinline__ void cp16(uint32_t dst, const void* src) {
    asm volatile("cp.async.cg.shared.global [%0], [%1], 16;\n" :: "r"(dst), "l"(src));
}
__device__ __forceinline__ void ldsm4(uint32_t* r, uint32_t addr) {
    asm volatile("ldmatrix.sync.aligned.m8n8.x4.shared.b16 {%0,%1,%2,%3}, [%4];"
                 : "=r"(r[0]), "=r"(r[1]), "=r"(r[2]), "=r"(r[3]) : "r"(addr));
}
__device__ __forceinline__ void mma_bf16(float* c, const uint32_t* a, const uint32_t* b) {
    asm volatile(
        "mma.sync.aligned.m16n8k16.row.col.f32.bf16.bf16.f32 "
        "{%0,%1,%2,%3},{%4,%5,%6,%7},{%8,%9},{%0,%1,%2,%3};"
        : "+f"(c[0]), "+f"(c[1]), "+f"(c[2]), "+f"(c[3])
        : "r"(a[0]), "r"(a[1]), "r"(a[2]), "r"(a[3]), "r"(b[0]), "r"(b[1]));
}
// Last chunk waits for its OWN group (wait_group 0); earlier leave prefetch in flight.
__device__ __forceinline__ void cp_wait(bool last) {
    if (last) asm volatile("cp.async.wait_group 0;" ::: "memory");
    else      asm volatile("cp.async.wait_group 1;" ::: "memory");
}
// Unpack 8 bf16 (uint4) -> two float4
__device__ __forceinline__ void unpack8_f4(uint4 u, float4& lo, float4& hi) {
    uint32_t w[4] = {u.x, u.y, u.z, u.w};
    float2 t0 = __bfloat1622float2(*reinterpret_cast<__nv_bfloat162*>(&w[0]));
    float2 t1 = __bfloat1622float2(*reinterpret_cast<__nv_bfloat162*>(&w[1]));
    float2 t2 = __bfloat1622float2(*reinterpret_cast<__nv_bfloat162*>(&w[2]));
    float2 t3 = __bfloat1622float2(*reinterpret_cast<__nv_bfloat162*>(&w[3]));
    lo = make_float4(t0.x, t0.y, t1.x, t1.y);
    hi = make_float4(t2.x, t2.y, t3.x, t3.y);
}

// ---------------------------------------------------------------------------
// Plain GEMM mainloop body (tile 256x64x32, 8 warps 4m x 2n, 3-stage).
// ---------------------------------------------------------------------------
#define GA_STAGE 16384
#define GB_STAGE 4096
#define GB_BASE  (3 * GA_STAGE)
#define GEMM_SMEM (3 * GA_STAGE + 3 * GB_STAGE)  // 61440

#define PLAIN_MAINLOOP(Aptr, Wptr, Kval)                                          \
    float acc[4][4][4];                                                           \
    _Pragma("unroll")                                                             \
    for (int mt = 0; mt < 4; mt++)                                                \
        _Pragma("unroll")                                                         \
        for (int nt = 0; nt < 4; nt++)                                            \
            _Pragma("unroll")                                                     \
            for (int r = 0; r < 4; r++) acc[mt][nt][r] = 0.f;                     \
    auto stage = [&](int kt, int buf) {                                           \
        const int k0 = kt * 32;                                                   \
        const uint32_t aB = sbase + buf * GA_STAGE;                               \
        const uint32_t bB = sbase + GB_BASE + buf * GB_STAGE;                     \
        _Pragma("unroll")                                                         \
        for (int i = 0; i < 4; i++) {                                             \
            int idx = i * 256 + tid;                                              \
            int row = idx >> 2, ch = idx & 3;                                     \
            cp16(aB + row * 64 + ((ch ^ ((row >> 1) & 3)) * 16),                  \
                 (Aptr) + (size_t)(m0 + row) * (Kval) + k0 + ch * 8);             \
        }                                                                         \
        {                                                                         \
            int row = tid >> 2, ch = tid & 3;                                     \
            cp16(bB + row * 64 + ((ch ^ ((row >> 1) & 3)) * 16),                  \
                 (Wptr) + (size_t)(n0 + row) * (Kval) + k0 + ch * 8);             \
        }                                                                         \
        asm volatile("cp.async.commit_group;" ::: "memory");                      \
    };                                                                            \
    const int nk = (Kval) >> 5;                                                   \
    stage(0, 0);                                                                  \
    stage(1, 1);                                                                  \
    for (int t = 0; t < nk; t++) {                                                \
        const int buf = t % 3;                                                    \
        cp_wait(t == nk - 1);                                                     \
        __syncthreads();                                                          \
        const uint32_t aB = sbase + buf * GA_STAGE;                               \
        const uint32_t bB = sbase + GB_BASE + buf * GB_STAGE;                     \
        _Pragma("unroll")                                                         \
        for (int ks = 0; ks < 2; ks++) {                                          \
            uint32_t af[4][4], bf[4][2];                                          \
            _Pragma("unroll")                                                     \
            for (int mt = 0; mt < 4; mt++) {                                      \
                int row = wm + mt * 16 + (lane & 15);                             \
                int ch = ks * 2 + (lane >> 4);                                    \
                ldsm4(af[mt], aB + row * 64 + ((ch ^ ((row >> 1) & 3)) * 16));    \
            }                                                                     \
            _Pragma("unroll")                                                     \
            for (int p = 0; p < 2; p++) {                                         \
                int row = wn + p * 16 + ((lane >> 4) << 3) + (lane & 7);          \
                int ch = ks * 2 + ((lane >> 3) & 1);                              \
                uint32_t r4[4];                                                   \
                ldsm4(r4, bB + row * 64 + ((ch ^ ((row >> 1) & 3)) * 16));        \
                bf[p * 2 + 0][0] = r4[0]; bf[p * 2 + 0][1] = r4[1];               \
                bf[p * 2 + 1][0] = r4[2]; bf[p * 2 + 1][1] = r4[3];               \
            }                                                                     \
            _Pragma("unroll")                                                     \
            for (int mt = 0; mt < 4; mt++)                                        \
                _Pragma("unroll")                                                 \
                for (int nt = 0; nt < 4; nt++)                                    \
                    mma_bf16(acc[mt][nt], af[mt], bf[nt]);                        \
        }                                                                         \
        __syncthreads();                                                          \
        if (t + 2 < nk) stage(t + 2, (t + 2) % 3);                                \
    }

// ---------------------------------------------------------------------------
// Plain bf16 GEMM (lin1): D[M,Nc] = A @ W^T + bias (opt ReLU)
// ---------------------------------------------------------------------------
template <typename OutT, bool RELU>
__global__ __launch_bounds__(256) void gemm_bf16_kernel(
        const __nv_bfloat16* __restrict__ A,
        const __nv_bfloat16* __restrict__ W,
        const float* __restrict__ bias,
        OutT* __restrict__ D,
        int K, int Nc) {
    extern __shared__ unsigned char smem[];
    const uint32_t sbase = (uint32_t)__cvta_generic_to_shared(smem);
    const int tid = threadIdx.x;
    const int lane = tid & 31;
    const int wid = tid >> 5;
    const int wm = (wid & 3) * 64;
    const int wn = (wid >> 2) * 32;
    const int m0 = blockIdx.y * 256;
    const int n0 = blockIdx.x * 64;

    PLAIN_MAINLOOP(A, W, K)

#pragma unroll
    for (int mt = 0; mt < 4; mt++) {
#pragma unroll
        for (int nt = 0; nt < 4; nt++) {
            int m = m0 + wm + mt * 16 + (lane >> 2);
            int n = n0 + wn + nt * 8 + (lane & 3) * 2;
            float b0 = bias[n], b1 = bias[n + 1];
            float v0 = acc[mt][nt][0] + b0;
            float v1 = acc[mt][nt][1] + b1;
            float v2 = acc[mt][nt][2] + b0;
            float v3 = acc[mt][nt][3] + b1;
            if (RELU) {
                v0 = fmaxf(v0, 0.f); v1 = fmaxf(v1, 0.f);
                v2 = fmaxf(v2, 0.f); v3 = fmaxf(v3, 0.f);
            }
            if constexpr (sizeof(OutT) == 2) {
                *reinterpret_cast<__nv_bfloat162*>((__nv_bfloat16*)D + (size_t)m * Nc + n) =
                    __floats2bfloat162_rn(v0, v1);
                *reinterpret_cast<__nv_bfloat162*>((__nv_bfloat16*)D + (size_t)(m + 8) * Nc + n) =
                    __floats2bfloat162_rn(v2, v3);
            } else {
                *reinterpret_cast<float2*>((float*)D + (size_t)m * Nc + n) = make_float2(v0, v1);
                *reinterpret_cast<float2*>((float*)D + (size_t)(m + 8) * Nc + n) = make_float2(v2, v3);
            }
        }
    }
}

// ---------------------------------------------------------------------------
// Merged QKV GEMM: Nc spans 576 (Wq|Wk|Wv rows contiguous).
// ---------------------------------------------------------------------------
__global__ __launch_bounds__(256) void qkv_gemm_kernel(
        const __nv_bfloat16* __restrict__ Aq,
        const __nv_bfloat16* __restrict__ Af,
        const __nv_bfloat16* __restrict__ W,
        const float* __restrict__ bias,
        __nv_bfloat16* __restrict__ Dqk,
        __nv_bfloat16* __restrict__ Dv) {
    extern __shared__ unsigned char smem[];
    const uint32_t sbase = (uint32_t)__cvta_generic_to_shared(smem);
    const int tid = threadIdx.x;
    const int lane = tid & 31;
    const int wid = tid >> 5;
    const int wm = (wid & 3) * 64;
    const int wn = (wid >> 2) * 32;
    const int m0 = blockIdx.y * 256;
    const int n0 = blockIdx.x * 64;

    const bool isV = (n0 >= 2 * CDIM);
    const __nv_bfloat16* A = isV ? Af : Aq;
    __nv_bfloat16* D = isV ? Dv : Dqk;
    const int dStride = isV ? CDIM : 2 * CDIM;
    const int dCol0 = isV ? n0 - 2 * CDIM : n0;

    PLAIN_MAINLOOP(A, W, CDIM)

#pragma unroll
    for (int mt = 0; mt < 4; mt++) {
#pragma unroll
        for (int nt = 0; nt < 4; nt++) {
            int m = m0 + wm + mt * 16 + (lane >> 2);
            int nl = wn + nt * 8 + (lane & 3) * 2;
            int n = n0 + nl;
            float b0 = bias[n], b1 = bias[n + 1];
            int nd = dCol0 + nl;
            *reinterpret_cast<__nv_bfloat162*>(D + (size_t)m * dStride + nd) =
                __floats2bfloat162_rn(acc[mt][nt][0] + b0, acc[mt][nt][1] + b1);
            *reinterpret_cast<__nv_bfloat162*>(D + (size_t)(m + 8) * dStride + nd) =
                __floats2bfloat162_rn(acc[mt][nt][2] + b0, acc[mt][nt][3] + b1);
        }
    }
}

// ---------------------------------------------------------------------------
// Fused GEMM mainloop config (tile 64 x 192, K chunks of 32, 3-stage).
// ---------------------------------------------------------------------------
#define FA_STAGE 4096
#define FB_STAGE 12288
#define FB_BASE  (3 * FA_STAGE)
#define FUSED_SMEM (3 * FA_STAGE + 3 * FB_STAGE)  // 49152

#define FUSED_MAINLOOP(Aptr, Wptr, Kval)                                              \
    float acc[2][6][4];                                                               \
    _Pragma("unroll")                                                                 \
    for (int mt = 0; mt < 2; mt++)                                                    \
        _Pragma("unroll")                                                             \
        for (int nt = 0; nt < 6; nt++)                                                \
            _Pragma("unroll")                                                         \
            for (int r = 0; r < 4; r++) acc[mt][nt][r] = 0.f;                         \
    auto stage = [&](int kt, int buf) {                                               \
        const int k0 = kt * 32;                                                       \
        {                                                                             \
            int row = tid >> 2, ch = tid & 3;                                         \
            cp16(sbase + buf * FA_STAGE + row * 64 + ((ch ^ ((row >> 1) & 3)) * 16),  \
                 (Aptr) + (size_t)(m0 + row) * (Kval) + k0 + ch * 8);                 \
        }                                                                             \
        _Pragma("unroll")                                                             \
        for (int i = 0; i < 3; i++) {                                                 \
            int idx = i * 256 + tid;                                                  \
            int row = idx >> 2, ch = idx & 3;                                         \
            cp16(sbase + FB_BASE + buf * FB_STAGE + row * 64 +                        \
                     ((ch ^ ((row >> 1) & 3)) * 16),                                  \
                 (Wptr) + (size_t)row * (Kval) + k0 + ch * 8);                        \
        }                                                                             \
        asm volatile("cp.async.commit_group;" ::: "memory");                          \
    };                                                                                \
    const int nk = (Kval) >> 5;                                                       \
    stage(0, 0);                                                                      \
    stage(1, 1);                                                                      \
    for (int t = 0; t < nk; t++) {                                                    \
        const int buf = t % 3;                                                        \
        cp_wait(t == nk - 1);                                                         \
        __syncthreads();                                                              \
        const uint32_t aB = sbase + buf * FA_STAGE;                                   \
        const uint32_t bB = sbase + FB_BASE + buf * FB_STAGE;                         \
        _Pragma("unroll")                                                             \
        for (int ks = 0; ks < 2; ks++) {                                              \
            uint32_t af[2][4], bf[6][2];                                              \
            _Pragma("unroll")                                                         \
            for (int mt = 0; mt < 2; mt++) {                                          \
                int row = wm + mt * 16 + (lane & 15);                                 \
                int ch = ks * 2 + (lane >> 4);                                        \
                ldsm4(af[mt], aB + row * 64 + ((ch ^ ((row >> 1) & 3)) * 16));        \
            }                                                                         \
            _Pragma("unroll")                                                         \
            for (int p = 0; p < 3; p++) {                                             \
                int row = wn + p * 16 + ((lane >> 4) << 3) + (lane & 7);              \
                int ch = ks * 2 + ((lane >> 3) & 1);                                  \
                uint32_t r4[4];                                                       \
                ldsm4(r4, bB + row * 64 + ((ch ^ ((row >> 1) & 3)) * 16));            \
                bf[p * 2 + 0][0] = r4[0]; bf[p * 2 + 0][1] = r4[1];                   \
                bf[p * 2 + 1][0] = r4[2]; bf[p * 2 + 1][1] = r4[3];                   \
            }                                                                         \
            _Pragma("unroll")                                                         \
            for (int mt = 0; mt < 2; mt++)                                            \
                _Pragma("unroll")                                                     \
                for (int nt = 0; nt < 6; nt++)                                        \
                    mma_bf16(acc[mt][nt], af[mt], bf[nt]);                            \
        }                                                                             \
        __syncthreads();                                                              \
        if (t + 2 < nk) stage(t + 2, (t + 2) % 3);                                    \
    }

// ---------------------------------------------------------------------------
// Fused out_proj + scatter + residual + LN1.
// ---------------------------------------------------------------------------
__global__ __launch_bounds__(256) void gemm_op_ln1_kernel(
        const __nv_bfloat16* __restrict__ A,
        const __nv_bfloat16* __restrict__ W,
        const float* __restrict__ bias,
        const float* __restrict__ cur,
        const int* __restrict__ inds_all, const int* __restrict__ block_id, int layer,
        const float* __restrict__ lnw, const float* __restrict__ lnb,
        float* __restrict__ x32, __nv_bfloat16* __restrict__ x16) {
    extern __shared__ unsigned char smem[];
    const uint32_t sbase = (uint32_t)__cvta_generic_to_shared(smem);
    const int tid = threadIdx.x;
    const int lane = tid & 31;
    const int wid = tid >> 5;
    const int wm = (wid & 1) * 32;
    const int wn = (wid >> 1) * 48;
    const int m0 = blockIdx.x * 64;

    FUSED_MAINLOOP(A, W, CDIM)

    float* stats = reinterpret_cast<float*>(smem);
    const int gid = lane >> 2, tig = lane & 3;
    const int shift = block_id[0] & 1;
    const int* ip = inds_all + ((size_t)shift * 2 + layer) * NVOX;
    int vrow[2][2];
#pragma unroll
    for (int mt = 0; mt < 2; mt++) {
#pragma unroll
        for (int mm = 0; mm < 2; mm++) {
            int rloc = wm + mt * 16 + mm * 8 + gid;
            int v = ip[m0 + rloc];
            vrow[mt][mm] = v;
            float s = 0.f, s2 = 0.f;
#pragma unroll
            for (int nt = 0; nt < 6; nt++) {
                int n = wn + nt * 8 + tig * 2;
                float2 c = *reinterpret_cast<const float2*>(cur + (size_t)v * CDIM + n);
                float a0 = acc[mt][nt][mm * 2]     + bias[n]     + c.x;
                float a1 = acc[mt][nt][mm * 2 + 1] + bias[n + 1] + c.y;
                acc[mt][nt][mm * 2] = a0; acc[mt][nt][mm * 2 + 1] = a1;
                s += a0 + a1; s2 += a0 * a0 + a1 * a1;
            }
            s  += __shfl_xor_sync(0xffffffffu, s, 1);  s  += __shfl_xor_sync(0xffffffffu, s, 2);
            s2 += __shfl_xor_sync(0xffffffffu, s2, 1); s2 += __shfl_xor_sync(0xffffffffu, s2, 2);
            if (tig == 0) {
                stats[((wid >> 1) * 64 + rloc) * 2]     = s;
                stats[((wid >> 1) * 64 + rloc) * 2 + 1] = s2;
            }
        }
    }
    __syncthreads();
#pragma unroll
    for (int mt = 0; mt < 2; mt++) {
#pragma unroll
        for (int mm = 0; mm < 2; mm++) {
            int rloc = wm + mt * 16 + mm * 8 + gid;
            int v = vrow[mt][mm];
            float S = 0.f, S2 = 0.f;
#pragma unroll
            for (int g = 0; g < 4; g++) {
                S  += stats[(g * 64 + rloc) * 2];
                S2 += stats[(g * 64 + rloc) * 2 + 1];
            }
            float mean = S * (1.0f / CDIM);
            float var = S2 * (1.0f / CDIM) - mean * mean;
            float rs = rsqrtf(var + 1e-5f);
#pragma unroll
            for (int nt = 0; nt < 6; nt++) {
                int n = wn + nt * 8 + tig * 2;
                float o0 = (acc[mt][nt][mm * 2]     - mean) * rs * lnw[n]     + lnb[n];
                float o1 = (acc[mt][nt][mm * 2 + 1] - mean) * rs * lnw[n + 1] + lnb[n + 1];
                *reinterpret_cast<float2*>(x32 + (size_t)v * CDIM + n) = make_float2(o0, o1);
                *reinterpret_cast<__nv_bfloat162*>(x16 + (size_t)v * CDIM + n) =
                    __floats2bfloat162_rn(o0, o1);
            }
        }
    }
}

// ---------------------------------------------------------------------------
// Fused lin2 + LN2 + LN3 (voxel-order rows).
// ---------------------------------------------------------------------------
__global__ __launch_bounds__(256) void gemm_ffn_ln23_kernel(
        const __nv_bfloat16* __restrict__ A,
        const __nv_bfloat16* __restrict__ W,
        const float* __restrict__ bias,
        const float* __restrict__ x32,
        const float* __restrict__ cur,
        const float* __restrict__ w2, const float* __restrict__ b2,
        const float* __restrict__ w3, const float* __restrict__ b3,
        float* __restrict__ outp) {
    extern __shared__ unsigned char smem[];
    const uint32_t sbase = (uint32_t)__cvta_generic_to_shared(smem);
    const int tid = threadIdx.x;
    const int lane = tid & 31;
    const int wid = tid >> 5;
    const int wm = (wid & 1) * 32;
    const int wn = (wid >> 1) * 48;
    const int m0 = blockIdx.x * 64;

    FUSED_MAINLOOP(A, W, DFF)

    float* stats = reinterpret_cast<float*>(smem);
    const int gid = lane >> 2, tig = lane & 3;

#pragma unroll
    for (int mt = 0; mt < 2; mt++) {
#pragma unroll
        for (int mm = 0; mm < 2; mm++) {
            int rloc = wm + mt * 16 + mm * 8 + gid;
            int v = m0 + rloc;
            float s = 0.f, s2 = 0.f;
#pragma unroll
            for (int nt = 0; nt < 6; nt++) {
                int n = wn + nt * 8 + tig * 2;
                float2 xr = *reinterpret_cast<const float2*>(x32 + (size_t)v * CDIM + n);
                float a0 = acc[mt][nt][mm * 2]     + bias[n]     + xr.x;
                float a1 = acc[mt][nt][mm * 2 + 1] + bias[n + 1] + xr.y;
                acc[mt][nt][mm * 2] = a0; acc[mt][nt][mm * 2 + 1] = a1;
                s += a0 + a1; s2 += a0 * a0 + a1 * a1;
            }
            s  += __shfl_xor_sync(0xffffffffu, s, 1);  s  += __shfl_xor_sync(0xffffffffu, s, 2);
            s2 += __shfl_xor_sync(0xffffffffu, s2, 1); s2 += __shfl_xor_sync(0xffffffffu, s2, 2);
            if (tig == 0) {
                stats[((wid >> 1) * 64 + rloc) * 2]     = s;
                stats[((wid >> 1) * 64 + rloc) * 2 + 1] = s2;
            }
        }
    }
    __syncthreads();

    float sB[2][2], s2B[2][2];
#pragma unroll
    for (int mt = 0; mt < 2; mt++) {
#pragma unroll
        for (int mm = 0; mm < 2; mm++) {
            int rloc = wm + mt * 16 + mm * 8 + gid;
            int v = m0 + rloc;
            float S = 0.f, S2 = 0.f;
#pragma unroll
            for (int g = 0; g < 4; g++) {
                S  += stats[(g * 64 + rloc) * 2];
                S2 += stats[(g * 64 + rloc) * 2 + 1];
            }
            float mean = S * (1.0f / CDIM);
            float var = S2 * (1.0f / CDIM) - mean * mean;
            float rs = rsqrtf(var + 1e-5f);
            float s = 0.f, s2 = 0.f;
#pragma unroll
            for (int nt = 0; nt < 6; nt++) {
                int n = wn + nt * 8 + tig * 2;
                float2 cv = *reinterpret_cast<const float2*>(cur + (size_t)v * CDIM + n);
                float t0 = (acc[mt][nt][mm * 2]     - mean) * rs * w2[n]     + b2[n]     + cv.x;
                float t1 = (acc[mt][nt][mm * 2 + 1] - mean) * rs * w2[n + 1] + b2[n + 1] + cv.y;
                acc[mt][nt][mm * 2] = t0; acc[mt][nt][mm * 2 + 1] = t1;
                s += t0 + t1; s2 += t0 * t0 + t1 * t1;
            }
            s  += __shfl_xor_sync(0xffffffffu, s, 1);  s  += __shfl_xor_sync(0xffffffffu, s, 2);
            s2 += __shfl_xor_sync(0xffffffffu, s2, 1); s2 += __shfl_xor_sync(0xffffffffu, s2, 2);
            sB[mt][mm] = s; s2B[mt][mm] = s2;
        }
    }
    __syncthreads();
#pragma unroll
    for (int mt = 0; mt < 2; mt++)
#pragma unroll
        for (int mm = 0; mm < 2; mm++) {
            int rloc = wm + mt * 16 + mm * 8 + gid;
            if (tig == 0) {
                stats[((wid >> 1) * 64 + rloc) * 2]     = sB[mt][mm];
                stats[((wid >> 1) * 64 + rloc) * 2 + 1] = s2B[mt][mm];
            }
        }
    __syncthreads();

#pragma unroll
    for (int mt = 0; mt < 2; mt++) {
#pragma unroll
        for (int mm = 0; mm < 2; mm++) {
            int rloc = wm + mt * 16 + mm * 8 + gid;
            int v = m0 + rloc;
            float S = 0.f, S2 = 0.f;
#pragma unroll
            for (int g = 0; g < 4; g++) {
                S  += stats[(g * 64 + rloc) * 2];
                S2 += stats[(g * 64 + rloc) * 2 + 1];
            }
            float mean = S * (1.0f / CDIM);
            float var = S2 * (1.0f / CDIM) - mean * mean;
            float rs = rsqrtf(var + 1e-5f);
#pragma unroll
            for (int nt = 0; nt < 6; nt++) {
                int n = wn + nt * 8 + tig * 2;
                float o0 = (acc[mt][nt][mm * 2]     - mean) * rs * w3[n]     + b3[n];
                float o1 = (acc[mt][nt][mm * 2 + 1] - mean) * rs * w3[n + 1] + b3[n + 1];
                *reinterpret_cast<float2*>(outp + (size_t)v * CDIM + n) = make_float2(o0, o1);
            }
        }
    }
}

// ---------------------------------------------------------------------------
// Single merged weight converter
// ---------------------------------------------------------------------------
__global__ void cvt_all_kernel(const float* __restrict__ ipw,
                               const float* __restrict__ opw,
                               const float* __restrict__ l1w,
                               const float* __restrict__ l2w,
                               __nv_bfloat16* __restrict__ dst) {
    int i = blockIdx.x * blockDim.x + threadIdx.x;
    const int N4 = W16_TOT / 4;
    if (i >= N4) return;
    int e = i * 4;
    const float* src;
    int off;
    if (e < OPW_OFF)      { src = ipw; off = e - IPW_OFF; }
    else if (e < L1W_OFF) { src = opw; off = e - OPW_OFF; }
    else if (e < L2W_OFF) { src = l1w; off = e - L1W_OFF; }
    else                  { src = l2w; off = e - L2W_OFF; }
    float4 v = *reinterpret_cast<const float4*>(src + off);
    reinterpret_cast<__nv_bfloat162*>(dst)[i * 2 + 0] = __floats2bfloat162_rn(v.x, v.y);
    reinterpret_cast<__nv_bfloat162*>(dst)[i * 2 + 1] = __floats2bfloat162_rn(v.z, v.w);
}

// ---------------------------------------------------------------------------
// Prep (coalesced, voxel order): qin16 = bf16(cur+pos); feat16 = bf16(cur)
// ---------------------------------------------------------------------------
__global__ void prep_kernel(const float* __restrict__ cur,
                            const float* __restrict__ pos,
                            __nv_bfloat16* __restrict__ qin,
                            __nv_bfloat16* __restrict__ feat) {
    int gid = blockIdx.x * blockDim.x + threadIdx.x;
    const int TOT = NVOX * (CDIM / 4);
    if (gid >= TOT) return;
    float4 f = reinterpret_cast<const float4*>(cur)[gid];
    float4 pp = reinterpret_cast<const float4*>(pos)[gid];
    __nv_bfloat162* f2 = reinterpret_cast<__nv_bfloat162*>(feat);
    __nv_bfloat162* q2 = reinterpret_cast<__nv_bfloat162*>(qin);
    f2[gid * 2 + 0] = __floats2bfloat162_rn(f.x, f.y);
    f2[gid * 2 + 1] = __floats2bfloat162_rn(f.z, f.w);
    q2[gid * 2 + 0] = __floats2bfloat162_rn(f.x + pp.x, f.y + pp.y);
    q2[gid * 2 + 1] = __floats2bfloat162_rn(f.z + pp.z, f.w + pp.w);
}

// ---------------------------------------------------------------------------
// Attention: one block per set, 288 threads = (36 rows x 8 heads).
// K/V staged in smem as FP32 (unpacked once at fill). Q loaded per-thread
// straight from global (each thread needs only its own 24-element row).
// No Q smem -> 55.4 KB/block -> 4 CTAs/SM.
// ---------------------------------------------------------------------------
#define ATTN_SMEM (2 * SETSZ * CDIM * 4 + 160)

__global__ __launch_bounds__(288) void attn_kernel(const __nv_bfloat16* __restrict__ qk,
                                                   const __nv_bfloat16* __restrict__ v,
                                                   const int* __restrict__ inds_all,
                                                   const int* __restrict__ block_id,
                                                   int layer,
                                                   __nv_bfloat16* __restrict__ o) {
    extern __shared__ float smf[];
    float* ks = smf;                      // 36 x 192 fp32
    float* vs = smf + SETSZ * CDIM;       // 36 x 192 fp32
    int* vids = reinterpret_cast<int*>(smf + 2 * SETSZ * CDIM);

    int s = blockIdx.x;
    int tid = threadIdx.x;

    if (tid < SETSZ) {
        int shift = block_id[0] & 1;
        vids[tid] = inds_all[((size_t)shift * 2 + layer) * NVOX + s * SETSZ + tid];
    }
    __syncthreads();

    const uint4* qk4 = reinterpret_cast<const uint4*>(qk);
    const uint4* v4 = reinterpret_cast<const uint4*>(v);

    // Fill K (qk row chunks 24..47) and V (24 chunks/row), unpack to fp32
    for (int idx = tid; idx < SETSZ * 24; idx += 288) {
        int row = idx / 24, c = idx % 24;
        uint4 u = qk4[(size_t)vids[row] * 48 + 24 + c];
        float4 lo, hi;
        unpack8_f4(u, lo, hi);
        float* dst = ks + row * CDIM + c * 8;
        reinterpret_cast<float4*>(dst)[0] = lo;
        reinterpret_cast<float4*>(dst)[1] = hi;
    }
    for (int idx = tid; idx < SETSZ * 24; idx += 288) {
        int row = idx / 24, c = idx % 24;
        uint4 u = v4[(size_t)vids[row] * 24 + c];
        float4 lo, hi;
        unpack8_f4(u, lo, hi);
        float* dst = vs + row * CDIM + c * 8;
        reinterpret_cast<float4*>(dst)[0] = lo;
        reinterpret_cast<float4*>(dst)[1] = hi;
    }

    int l = tid % SETSZ;
    int h = tid / SETSZ;

    // Per-thread Q row straight from global: q part = chunks h*3 .. h*3+2
    float qr[DH];
    {
        const uint4* qrow = qk4 + (size_t)vids[l] * 48 + h * 3;
#pragma unroll
        for (int c = 0; c < 3; c++) {
            float4 lo, hi;
            unpack8_f4(qrow[c], lo, hi);
            qr[c * 8 + 0] = lo.x; qr[c * 8 + 1] = lo.y;
            qr[c * 8 + 2] = lo.z; qr[c * 8 + 3] = lo.w;
            qr[c * 8 + 4] = hi.x; qr[c * 8 + 5] = hi.y;
            qr[c * 8 + 6] = hi.z; qr[c * 8 + 7] = hi.w;
        }
    }
    __syncthreads();

    const float scale = 0.20412414523193154f;
    float sc[SETSZ];
    float mx = -1e30f;
#pragma unroll 4
    for (int m = 0; m < SETSZ; m++) {
        const float4* krow = reinterpret_cast<const float4*>(ks + m * CDIM + h * DH);
        float dot = 0.f;
#pragma unroll
        for (int c = 0; c < 6; c++) {
            float4 t = krow[c];
            dot += qr[c * 4 + 0] * t.x + qr[c * 4 + 1] * t.y
                 + qr[c * 4 + 2] * t.z + qr[c * 4 + 3] * t.w;
        }
        dot *= scale;
        sc[m] = dot;
        mx = fmaxf(mx, dot);
    }
    float sum = 0.f;
#pragma unroll 4
    for (int m = 0; m < SETSZ; m++) {
        sc[m] = expf(sc[m] - mx);
        sum += sc[m];
    }
    float inv = 1.0f / sum;

    float acc[DH];
#pragma unroll
    for (int d = 0; d < DH; d++) acc[d] = 0.f;
#pragma unroll 4
    for (int m = 0; m < SETSZ; m++) {
        const float4* vrow = reinterpret_cast<const float4*>(vs + m * CDIM + h * DH);
        float p = sc[m];
#pragma unroll
        for (int c = 0; c < 6; c++) {
            float4 t = vrow[c];
            acc[c * 4 + 0] += p * t.x; acc[c * 4 + 1] += p * t.y;
            acc[c * 4 + 2] += p * t.z; acc[c * 4 + 3] += p * t.w;
        }
    }

    __nv_bfloat162* o2 = reinterpret_cast<__nv_bfloat162*>(
        o + (size_t)s * SETSZ * CDIM + l * CDIM + h * DH);
#pragma unroll
    for (int d2 = 0; d2 < DH / 2; d2++)
        o2[d2] = __floats2bfloat162_rn(acc[d2 * 2] * inv, acc[d2 * 2 + 1] * inv);
}

// ---------------------------------------------------------------------------
// Host orchestration
// ---------------------------------------------------------------------------
extern "C" void kernel_launch(void* const* d_in, const int* in_sizes, int n_in,
                              void* d_out, int out_size) {
    (void)in_sizes; (void)n_in; (void)out_size;
    const float* src  = (const float*)d_in[0];
    const int*   inds = (const int*)d_in[1];
    const float* pos  = (const float*)d_in[3];
    const int*   bid  = (const int*)d_in[4];
    const float* ipw  = (const float*)d_in[5];
    const float* ipb  = (const float*)d_in[6];
    const float* opw  = (const float*)d_in[7];
    const float* opb  = (const float*)d_in[8];
    const float* l1w  = (const float*)d_in[9];
    const float* l1b  = (const float*)d_in[10];
    const float* l2w  = (const float*)d_in[11];
    const float* l2b  = (const float*)d_in[12];
    const float* n1w  = (const float*)d_in[13];
    const float* n1b  = (const float*)d_in[14];
    const float* n2w  = (const float*)d_in[15];
    const float* n2b  = (const float*)d_in[16];
    const float* n3w  = (const float*)d_in[17];
    const float* n3b  = (const float*)d_in[18];

    float* out = (float*)d_out;

    __nv_bfloat16 *qk16, *qin16, *feat16, *v16, *x16, *h16, *w16;
    float *x32;
    cudaGetSymbolAddress((void**)&qk16, g_qk16);
    cudaGetSymbolAddress((void**)&qin16, g_qin16);
    cudaGetSymbolAddress((void**)&feat16, g_feat16);
    cudaGetSymbolAddress((void**)&v16, g_v16);
    cudaGetSymbolAddress((void**)&x16, g_x16);
    cudaGetSymbolAddress((void**)&h16, g_h16);
    cudaGetSymbolAddress((void**)&w16, g_w16);
    cudaGetSymbolAddress((void**)&x32, g_x32);

    cudaFuncSetAttribute((const void*)gemm_bf16_kernel<__nv_bfloat16, true>,
                         cudaFuncAttributeMaxDynamicSharedMemorySize, GEMM_SMEM);
    cudaFuncSetAttribute((const void*)qkv_gemm_kernel,
                         cudaFuncAttributeMaxDynamicSharedMemorySize, GEMM_SMEM);
    cudaFuncSetAttribute((const void*)gemm_op_ln1_kernel,
                         cudaFuncAttributeMaxDynamicSharedMemorySize, FUSED_SMEM);
    cudaFuncSetAttribute((const void*)gemm_ffn_ln23_kernel,
                         cudaFuncAttributeMaxDynamicSharedMemorySize, FUSED_SMEM);
    cudaFuncSetAttribute((const void*)attn_kernel,
                         cudaFuncAttributeMaxDynamicSharedMemorySize, ATTN_SMEM);

    cvt_all_kernel<<<(W16_TOT / 4 + 255) / 256, 256>>>(ipw, opw, l1w, l2w, w16);

    const int TOT4 = NVOX * (CDIM / 4);
    dim3 pgrid((TOT4 + 255) / 256);
    dim3 gridQKV(9, NVOX / 256);
    dim3 grid768(DFF / 64, NVOX / 256);
    dim3 fgrid(NVOX / 64);

    for (int i = 0; i < 2; i++) {
        const __nv_bfloat16* Wqkv = w16 + IPW_OFF + (size_t)i * 3 * CDIM * CDIM;
        const float* bqkv = ipb + (size_t)i * 3 * CDIM;
        const float* posL = pos + (size_t)i * NVOX * CDIM;
        const float* cur = (i == 0) ? src : out;

        prep_kernel<<<pgrid, 256>>>(cur, posL, qin16, feat16);

        qkv_gemm_kernel<<<gridQKV, 256, GEMM_SMEM>>>(
            qin16, feat16, Wqkv, bqkv, qk16, v16);

        attn_kernel<<<NSET, 288, ATTN_SMEM>>>(qk16, v16, inds, bid, i, qin16);

        gemm_op_ln1_kernel<<<fgrid, 256, FUSED_SMEM>>>(
            qin16, w16 + OPW_OFF + (size_t)i * CDIM * CDIM, opb + (size_t)i * CDIM,
            cur, inds, bid, i, n1w + i * CDIM, n1b + i * CDIM, x32, x16);

        gemm_bf16_kernel<__nv_bfloat16, true><<<grid768, 256, GEMM_SMEM>>>(
            x16, w16 + L1W_OFF + (size_t)i * DFF * CDIM, l1b + (size_t)i * DFF,
            h16, CDIM, DFF);

        gemm_ffn_ln23_kernel<<<fgrid, 256, FUSED_SMEM>>>(
            h16, w16 + L2W_OFF + (size_t)i * CDIM * DFF, l2b + (size_t)i * CDIM,
            x32, cur, n2w + i * CDIM, n2b + i * CDIM,
            n3w + i * CDIM, n3b + i * CDIM, out);
    }
}

// round 13
// speedup vs baseline: 1.0671x; 1.0054x over previous
#include <cuda_runtime.h>
#include <cuda_bf16.h>
#include <math.h>
#include <stdint.h>

// Problem constants
#define NVOX 147456
#define CDIM 192
#define NH 8
#define DH 24
#define DFF 768
#define SETSZ 36
#define NSET 4096

// ---------------------------------------------------------------------------
// Scratch (device globals)
// ---------------------------------------------------------------------------
__device__ __nv_bfloat16 g_qk16[(size_t)NVOX * 2 * CDIM];  // Q|K voxel-order (stride 384)
__device__ __nv_bfloat16 g_qin16[(size_t)NVOX * CDIM];     // q_in (voxel) / attn out (set)
__device__ __nv_bfloat16 g_feat16[(size_t)NVOX * CDIM];    // bf16(cur), voxel order
__device__ __nv_bfloat16 g_v16[(size_t)NVOX * CDIM];       // V, voxel order
__device__ __nv_bfloat16 g_x16[(size_t)NVOX * CDIM];
__device__ __nv_bfloat16 g_h16[(size_t)NVOX * DFF];
__device__ float g_x32[(size_t)NVOX * CDIM];   // post-LN1 x (fp32)
// bf16 weights: [ipw | opw | l1w | l2w]
#define IPW_OFF 0
#define OPW_OFF 221184
#define L1W_OFF 294912
#define L2W_OFF 589824
#define W16_TOT 884736
__device__ __nv_bfloat16 g_w16[W16_TOT];

// ---------------------------------------------------------------------------
// mma.sync helpers
// ---------------------------------------------------------------------------
__device__ __forceinline__ void cp16(uint32_t dst, const void* src) {
    asm volatile("cp.async.cg.shared.global [%0], [%1], 16;\n" :: "r"(dst), "l"(src));
}
__device__ __forceinline__ void ldsm4(uint32_t* r, uint32_t addr) {
    asm volatile("ldmatrix.sync.aligned.m8n8.x4.shared.b16 {%0,%1,%2,%3}, [%4];"
                 : "=r"(r[0]), "=r"(r[1]), "=r"(r[2]), "=r"(r[3]) : "r"(addr));
}
__device__ __forceinline__ void mma_bf16(float* c, const uint32_t* a, const uint32_t* b) {
    asm volatile(
        "mma.sync.aligned.m16n8k16.row.col.f32.bf16.bf16.f32 "
        "{%0,%1,%2,%3},{%4,%5,%6,%7},{%8,%9},{%0,%1,%2,%3};"
        : "+f"(c[0]), "+f"(c[1]), "+f"(c[2]), "+f"(c[3])
        : "r"(a[0]), "r"(a[1]), "r"(a[2]), "r"(a[3]), "r"(b[0]), "r"(b[1]));
}
// Last chunk waits for its OWN group (wait_group 0); earlier leave prefetch in flight.
__device__ __forceinline__ void cp_wait(bool last) {
    if (last) asm volatile("cp.async.wait_group 0;" ::: "memory");
    else      asm volatile("cp.async.wait_group 1;" ::: "memory");
}
// Unpack 8 bf16 (uint4) -> two float4
__device__ __forceinline__ void unpack8_f4(uint4 u, float4& lo, float4& hi) {
    uint32_t w[4] = {u.x, u.y, u.z, u.w};
    float2 t0 = __bfloat1622float2(*reinterpret_cast<__nv_bfloat162*>(&w[0]));
    float2 t1 = __bfloat1622float2(*reinterpret_cast<__nv_bfloat162*>(&w[1]));
    float2 t2 = __bfloat1622float2(*reinterpret_cast<__nv_bfloat162*>(&w[2]));
    float2 t3 = __bfloat1622float2(*reinterpret_cast<__nv_bfloat162*>(&w[3]));
    lo = make_float4(t0.x, t0.y, t1.x, t1.y);
    hi = make_float4(t2.x, t2.y, t3.x, t3.y);
}

// ---------------------------------------------------------------------------
// Plain GEMM mainloop body (tile 256x64x32, 8 warps 4m x 2n, 3-stage).
// ---------------------------------------------------------------------------
#define GA_STAGE 16384
#define GB_STAGE 4096
#define GB_BASE  (3 * GA_STAGE)
#define GEMM_SMEM (3 * GA_STAGE + 3 * GB_STAGE)  // 61440

#define PLAIN_MAINLOOP(Aptr, Wptr, Kval)                                          \
    float acc[4][4][4];                                                           \
    _Pragma("unroll")                                                             \
    for (int mt = 0; mt < 4; mt++)                                                \
        _Pragma("unroll")                                                         \
        for (int nt = 0; nt < 4; nt++)                                            \
            _Pragma("unroll")                                                     \
            for (int r = 0; r < 4; r++) acc[mt][nt][r] = 0.f;                     \
    auto stage = [&](int kt, int buf) {                                           \
        const int k0 = kt * 32;                                                   \
        const uint32_t aB = sbase + buf * GA_STAGE;                               \
        const uint32_t bB = sbase + GB_BASE + buf * GB_STAGE;                     \
        _Pragma("unroll")                                                         \
        for (int i = 0; i < 4; i++) {                                             \
            int idx = i * 256 + tid;                                              \
            int row = idx >> 2, ch = idx & 3;                                     \
            cp16(aB + row * 64 + ((ch ^ ((row >> 1) & 3)) * 16),                  \
                 (Aptr) + (size_t)(m0 + row) * (Kval) + k0 + ch * 8);             \
        }                                                                         \
        {                                                                         \
            int row = tid >> 2, ch = tid & 3;                                     \
            cp16(bB + row * 64 + ((ch ^ ((row >> 1) & 3)) * 16),                  \
                 (Wptr) + (size_t)(n0 + row) * (Kval) + k0 + ch * 8);             \
        }                                                                         \
        asm volatile("cp.async.commit_group;" ::: "memory");                      \
    };                                                                            \
    const int nk = (Kval) >> 5;                                                   \
    stage(0, 0);                                                                  \
    stage(1, 1);                                                                  \
    for (int t = 0; t < nk; t++) {                                                \
        const int buf = t % 3;                                                    \
        cp_wait(t == nk - 1);                                                     \
        __syncthreads();                                                          \
        const uint32_t aB = sbase + buf * GA_STAGE;                               \
        const uint32_t bB = sbase + GB_BASE + buf * GB_STAGE;                     \
        _Pragma("unroll")                                                         \
        for (int ks = 0; ks < 2; ks++) {                                          \
            uint32_t af[4][4], bf[4][2];                                          \
            _Pragma("unroll")                                                     \
            for (int mt = 0; mt < 4; mt++) {                                      \
                int row = wm + mt * 16 + (lane & 15);                             \
                int ch = ks * 2 + (lane >> 4);                                    \
                ldsm4(af[mt], aB + row * 64 + ((ch ^ ((row >> 1) & 3)) * 16));    \
            }                                                                     \
            _Pragma("unroll")                                                     \
            for (int p = 0; p < 2; p++) {                                         \
                int row = wn + p * 16 + ((lane >> 4) << 3) + (lane & 7);          \
                int ch = ks * 2 + ((lane >> 3) & 1);                              \
                uint32_t r4[4];                                                   \
                ldsm4(r4, bB + row * 64 + ((ch ^ ((row >> 1) & 3)) * 16));        \
                bf[p * 2 + 0][0] = r4[0]; bf[p * 2 + 0][1] = r4[1];               \
                bf[p * 2 + 1][0] = r4[2]; bf[p * 2 + 1][1] = r4[3];               \
            }                                                                     \
            _Pragma("unroll")                                                     \
            for (int mt = 0; mt < 4; mt++)                                        \
                _Pragma("unroll")                                                 \
                for (int nt = 0; nt < 4; nt++)                                    \
                    mma_bf16(acc[mt][nt], af[mt], bf[nt]);                        \
        }                                                                         \
        __syncthreads();                                                          \
        if (t + 2 < nk) stage(t + 2, (t + 2) % 3);                                \
    }

// ---------------------------------------------------------------------------
// Plain bf16 GEMM (lin1): D[M,Nc] = A @ W^T + bias (opt ReLU)
// ---------------------------------------------------------------------------
template <typename OutT, bool RELU>
__global__ __launch_bounds__(256) void gemm_bf16_kernel(
        const __nv_bfloat16* __restrict__ A,
        const __nv_bfloat16* __restrict__ W,
        const float* __restrict__ bias,
        OutT* __restrict__ D,
        int K, int Nc) {
    extern __shared__ unsigned char smem[];
    const uint32_t sbase = (uint32_t)__cvta_generic_to_shared(smem);
    const int tid = threadIdx.x;
    const int lane = tid & 31;
    const int wid = tid >> 5;
    const int wm = (wid & 3) * 64;
    const int wn = (wid >> 2) * 32;
    const int m0 = blockIdx.y * 256;
    const int n0 = blockIdx.x * 64;

    PLAIN_MAINLOOP(A, W, K)

#pragma unroll
    for (int mt = 0; mt < 4; mt++) {
#pragma unroll
        for (int nt = 0; nt < 4; nt++) {
            int m = m0 + wm + mt * 16 + (lane >> 2);
            int n = n0 + wn + nt * 8 + (lane & 3) * 2;
            float b0 = bias[n], b1 = bias[n + 1];
            float v0 = acc[mt][nt][0] + b0;
            float v1 = acc[mt][nt][1] + b1;
            float v2 = acc[mt][nt][2] + b0;
            float v3 = acc[mt][nt][3] + b1;
            if (RELU) {
                v0 = fmaxf(v0, 0.f); v1 = fmaxf(v1, 0.f);
                v2 = fmaxf(v2, 0.f); v3 = fmaxf(v3, 0.f);
            }
            if constexpr (sizeof(OutT) == 2) {
                *reinterpret_cast<__nv_bfloat162*>((__nv_bfloat16*)D + (size_t)m * Nc + n) =
                    __floats2bfloat162_rn(v0, v1);
                *reinterpret_cast<__nv_bfloat162*>((__nv_bfloat16*)D + (size_t)(m + 8) * Nc + n) =
                    __floats2bfloat162_rn(v2, v3);
            } else {
                *reinterpret_cast<float2*>((float*)D + (size_t)m * Nc + n) = make_float2(v0, v1);
                *reinterpret_cast<float2*>((float*)D + (size_t)(m + 8) * Nc + n) = make_float2(v2, v3);
            }
        }
    }
}

// ---------------------------------------------------------------------------
// Merged QKV GEMM: Nc spans 576 (Wq|Wk|Wv rows contiguous).
// ---------------------------------------------------------------------------
__global__ __launch_bounds__(256) void qkv_gemm_kernel(
        const __nv_bfloat16* __restrict__ Aq,
        const __nv_bfloat16* __restrict__ Af,
        const __nv_bfloat16* __restrict__ W,
        const float* __restrict__ bias,
        __nv_bfloat16* __restrict__ Dqk,
        __nv_bfloat16* __restrict__ Dv) {
    extern __shared__ unsigned char smem[];
    const uint32_t sbase = (uint32_t)__cvta_generic_to_shared(smem);
    const int tid = threadIdx.x;
    const int lane = tid & 31;
    const int wid = tid >> 5;
    const int wm = (wid & 3) * 64;
    const int wn = (wid >> 2) * 32;
    const int m0 = blockIdx.y * 256;
    const int n0 = blockIdx.x * 64;

    const bool isV = (n0 >= 2 * CDIM);
    const __nv_bfloat16* A = isV ? Af : Aq;
    __nv_bfloat16* D = isV ? Dv : Dqk;
    const int dStride = isV ? CDIM : 2 * CDIM;
    const int dCol0 = isV ? n0 - 2 * CDIM : n0;

    PLAIN_MAINLOOP(A, W, CDIM)

#pragma unroll
    for (int mt = 0; mt < 4; mt++) {
#pragma unroll
        for (int nt = 0; nt < 4; nt++) {
            int m = m0 + wm + mt * 16 + (lane >> 2);
            int nl = wn + nt * 8 + (lane & 3) * 2;
            int n = n0 + nl;
            float b0 = bias[n], b1 = bias[n + 1];
            int nd = dCol0 + nl;
            *reinterpret_cast<__nv_bfloat162*>(D + (size_t)m * dStride + nd) =
                __floats2bfloat162_rn(acc[mt][nt][0] + b0, acc[mt][nt][1] + b1);
            *reinterpret_cast<__nv_bfloat162*>(D + (size_t)(m + 8) * dStride + nd) =
                __floats2bfloat162_rn(acc[mt][nt][2] + b0, acc[mt][nt][3] + b1);
        }
    }
}

// ---------------------------------------------------------------------------
// Fused GEMM mainloop config (tile 64 x 192, K chunks of 32, 3-stage).
// ---------------------------------------------------------------------------
#define FA_STAGE 4096
#define FB_STAGE 12288
#define FB_BASE  (3 * FA_STAGE)
#define FUSED_SMEM (3 * FA_STAGE + 3 * FB_STAGE)  // 49152

#define FUSED_MAINLOOP(Aptr, Wptr, Kval)                                              \
    float acc[2][6][4];                                                               \
    _Pragma("unroll")                                                                 \
    for (int mt = 0; mt < 2; mt++)                                                    \
        _Pragma("unroll")                                                             \
        for (int nt = 0; nt < 6; nt++)                                                \
            _Pragma("unroll")                                                         \
            for (int r = 0; r < 4; r++) acc[mt][nt][r] = 0.f;                         \
    auto stage = [&](int kt, int buf) {                                               \
        const int k0 = kt * 32;                                                       \
        {                                                                             \
            int row = tid >> 2, ch = tid & 3;                                         \
            cp16(sbase + buf * FA_STAGE + row * 64 + ((ch ^ ((row >> 1) & 3)) * 16),  \
                 (Aptr) + (size_t)(m0 + row) * (Kval) + k0 + ch * 8);                 \
        }                                                                             \
        _Pragma("unroll")                                                             \
        for (int i = 0; i < 3; i++) {                                                 \
            int idx = i * 256 + tid;                                                  \
            int row = idx >> 2, ch = idx & 3;                                         \
            cp16(sbase + FB_BASE + buf * FB_STAGE + row * 64 +                        \
                     ((ch ^ ((row >> 1) & 3)) * 16),                                  \
                 (Wptr) + (size_t)row * (Kval) + k0 + ch * 8);                        \
        }                                                                             \
        asm volatile("cp.async.commit_group;" ::: "memory");                          \
    };                                                                                \
    const int nk = (Kval) >> 5;                                                       \
    stage(0, 0);                                                                      \
    stage(1, 1);                                                                      \
    for (int t = 0; t < nk; t++) {                                                    \
        const int buf = t % 3;                                                        \
        cp_wait(t == nk - 1);                                                         \
        __syncthreads();                                                              \
        const uint32_t aB = sbase + buf * FA_STAGE;                                   \
        const uint32_t bB = sbase + FB_BASE + buf * FB_STAGE;                         \
        _Pragma("unroll")                                                             \
        for (int ks = 0; ks < 2; ks++) {                                              \
            uint32_t af[2][4], bf[6][2];                                              \
            _Pragma("unroll")                                                         \
            for (int mt = 0; mt < 2; mt++) {                                          \
                int row = wm + mt * 16 + (lane & 15);                                 \
                int ch = ks * 2 + (lane >> 4);                                        \
                ldsm4(af[mt], aB + row * 64 + ((ch ^ ((row >> 1) & 3)) * 16));        \
            }                                                                         \
            _Pragma("unroll")                                                         \
            for (int p = 0; p < 3; p++) {                                             \
                int row = wn + p * 16 + ((lane >> 4) << 3) + (lane & 7);              \
                int ch = ks * 2 + ((lane >> 3) & 1);                                  \
                uint32_t r4[4];                                                       \
                ldsm4(r4, bB + row * 64 + ((ch ^ ((row >> 1) & 3)) * 16));            \
                bf[p * 2 + 0][0] = r4[0]; bf[p * 2 + 0][1] = r4[1];                   \
                bf[p * 2 + 1][0] = r4[2]; bf[p * 2 + 1][1] = r4[3];                   \
            }                                                                         \
            _Pragma("unroll")                                                         \
            for (int mt = 0; mt < 2; mt++)                                            \
                _Pragma("unroll")                                                     \
                for (int nt = 0; nt < 6; nt++)                                        \
                    mma_bf16(acc[mt][nt], af[mt], bf[nt]);                            \
        }                                                                             \
        __syncthreads();                                                              \
        if (t + 2 < nk) stage(t + 2, (t + 2) % 3);                                    \
    }

// ---------------------------------------------------------------------------
// Fused out_proj + scatter + residual + LN1.
// ---------------------------------------------------------------------------
__global__ __launch_bounds__(256) void gemm_op_ln1_kernel(
        const __nv_bfloat16* __restrict__ A,
        const __nv_bfloat16* __restrict__ W,
        const float* __restrict__ bias,
        const float* __restrict__ cur,
        const int* __restrict__ inds_all, const int* __restrict__ block_id, int layer,
        const float* __restrict__ lnw, const float* __restrict__ lnb,
        float* __restrict__ x32, __nv_bfloat16* __restrict__ x16) {
    extern __shared__ unsigned char smem[];
    const uint32_t sbase = (uint32_t)__cvta_generic_to_shared(smem);
    const int tid = threadIdx.x;
    const int lane = tid & 31;
    const int wid = tid >> 5;
    const int wm = (wid & 1) * 32;
    const int wn = (wid >> 1) * 48;
    const int m0 = blockIdx.x * 64;

    FUSED_MAINLOOP(A, W, CDIM)

    float* stats = reinterpret_cast<float*>(smem);
    const int gid = lane >> 2, tig = lane & 3;
    const int shift = block_id[0] & 1;
    const int* ip = inds_all + ((size_t)shift * 2 + layer) * NVOX;
    int vrow[2][2];
#pragma unroll
    for (int mt = 0; mt < 2; mt++) {
#pragma unroll
        for (int mm = 0; mm < 2; mm++) {
            int rloc = wm + mt * 16 + mm * 8 + gid;
            int v = ip[m0 + rloc];
            vrow[mt][mm] = v;
            float s = 0.f, s2 = 0.f;
#pragma unroll
            for (int nt = 0; nt < 6; nt++) {
                int n = wn + nt * 8 + tig * 2;
                float2 c = *reinterpret_cast<const float2*>(cur + (size_t)v * CDIM + n);
                float a0 = acc[mt][nt][mm * 2]     + bias[n]     + c.x;
                float a1 = acc[mt][nt][mm * 2 + 1] + bias[n + 1] + c.y;
                acc[mt][nt][mm * 2] = a0; acc[mt][nt][mm * 2 + 1] = a1;
                s += a0 + a1; s2 += a0 * a0 + a1 * a1;
            }
            s  += __shfl_xor_sync(0xffffffffu, s, 1);  s  += __shfl_xor_sync(0xffffffffu, s, 2);
            s2 += __shfl_xor_sync(0xffffffffu, s2, 1); s2 += __shfl_xor_sync(0xffffffffu, s2, 2);
            if (tig == 0) {
                stats[((wid >> 1) * 64 + rloc) * 2]     = s;
                stats[((wid >> 1) * 64 + rloc) * 2 + 1] = s2;
            }
        }
    }
    __syncthreads();
#pragma unroll
    for (int mt = 0; mt < 2; mt++) {
#pragma unroll
        for (int mm = 0; mm < 2; mm++) {
            int rloc = wm + mt * 16 + mm * 8 + gid;
            int v = vrow[mt][mm];
            float S = 0.f, S2 = 0.f;
#pragma unroll
            for (int g = 0; g < 4; g++) {
                S  += stats[(g * 64 + rloc) * 2];
                S2 += stats[(g * 64 + rloc) * 2 + 1];
            }
            float mean = S * (1.0f / CDIM);
            float var = S2 * (1.0f / CDIM) - mean * mean;
            float rs = rsqrtf(var + 1e-5f);
#pragma unroll
            for (int nt = 0; nt < 6; nt++) {
                int n = wn + nt * 8 + tig * 2;
                float o0 = (acc[mt][nt][mm * 2]     - mean) * rs * lnw[n]     + lnb[n];
                float o1 = (acc[mt][nt][mm * 2 + 1] - mean) * rs * lnw[n + 1] + lnb[n + 1];
                *reinterpret_cast<float2*>(x32 + (size_t)v * CDIM + n) = make_float2(o0, o1);
                *reinterpret_cast<__nv_bfloat162*>(x16 + (size_t)v * CDIM + n) =
                    __floats2bfloat162_rn(o0, o1);
            }
        }
    }
}

// ---------------------------------------------------------------------------
// Fused lin2 + LN2 + LN3 (voxel-order rows).
// ---------------------------------------------------------------------------
__global__ __launch_bounds__(256) void gemm_ffn_ln23_kernel(
        const __nv_bfloat16* __restrict__ A,
        const __nv_bfloat16* __restrict__ W,
        const float* __restrict__ bias,
        const float* __restrict__ x32,
        const float* __restrict__ cur,
        const float* __restrict__ w2, const float* __restrict__ b2,
        const float* __restrict__ w3, const float* __restrict__ b3,
        float* __restrict__ outp) {
    extern __shared__ unsigned char smem[];
    const uint32_t sbase = (uint32_t)__cvta_generic_to_shared(smem);
    const int tid = threadIdx.x;
    const int lane = tid & 31;
    const int wid = tid >> 5;
    const int wm = (wid & 1) * 32;
    const int wn = (wid >> 1) * 48;
    const int m0 = blockIdx.x * 64;

    FUSED_MAINLOOP(A, W, DFF)

    float* stats = reinterpret_cast<float*>(smem);
    const int gid = lane >> 2, tig = lane & 3;

#pragma unroll
    for (int mt = 0; mt < 2; mt++) {
#pragma unroll
        for (int mm = 0; mm < 2; mm++) {
            int rloc = wm + mt * 16 + mm * 8 + gid;
            int v = m0 + rloc;
            float s = 0.f, s2 = 0.f;
#pragma unroll
            for (int nt = 0; nt < 6; nt++) {
                int n = wn + nt * 8 + tig * 2;
                float2 xr = *reinterpret_cast<const float2*>(x32 + (size_t)v * CDIM + n);
                float a0 = acc[mt][nt][mm * 2]     + bias[n]     + xr.x;
                float a1 = acc[mt][nt][mm * 2 + 1] + bias[n + 1] + xr.y;
                acc[mt][nt][mm * 2] = a0; acc[mt][nt][mm * 2 + 1] = a1;
                s += a0 + a1; s2 += a0 * a0 + a1 * a1;
            }
            s  += __shfl_xor_sync(0xffffffffu, s, 1);  s  += __shfl_xor_sync(0xffffffffu, s, 2);
            s2 += __shfl_xor_sync(0xffffffffu, s2, 1); s2 += __shfl_xor_sync(0xffffffffu, s2, 2);
            if (tig == 0) {
                stats[((wid >> 1) * 64 + rloc) * 2]     = s;
                stats[((wid >> 1) * 64 + rloc) * 2 + 1] = s2;
            }
        }
    }
    __syncthreads();

    float sB[2][2], s2B[2][2];
#pragma unroll
    for (int mt = 0; mt < 2; mt++) {
#pragma unroll
        for (int mm = 0; mm < 2; mm++) {
            int rloc = wm + mt * 16 + mm * 8 + gid;
            int v = m0 + rloc;
            float S = 0.f, S2 = 0.f;
#pragma unroll
            for (int g = 0; g < 4; g++) {
                S  += stats[(g * 64 + rloc) * 2];
                S2 += stats[(g * 64 + rloc) * 2 + 1];
            }
            float mean = S * (1.0f / CDIM);
            float var = S2 * (1.0f / CDIM) - mean * mean;
            float rs = rsqrtf(var + 1e-5f);
            float s = 0.f, s2 = 0.f;
#pragma unroll
            for (int nt = 0; nt < 6; nt++) {
                int n = wn + nt * 8 + tig * 2;
                float2 cv = *reinterpret_cast<const float2*>(cur + (size_t)v * CDIM + n);
                float t0 = (acc[mt][nt][mm * 2]     - mean) * rs * w2[n]     + b2[n]     + cv.x;
                float t1 = (acc[mt][nt][mm * 2 + 1] - mean) * rs * w2[n + 1] + b2[n + 1] + cv.y;
                acc[mt][nt][mm * 2] = t0; acc[mt][nt][mm * 2 + 1] = t1;
                s += t0 + t1; s2 += t0 * t0 + t1 * t1;
            }
            s  += __shfl_xor_sync(0xffffffffu, s, 1);  s  += __shfl_xor_sync(0xffffffffu, s, 2);
            s2 += __shfl_xor_sync(0xffffffffu, s2, 1); s2 += __shfl_xor_sync(0xffffffffu, s2, 2);
            sB[mt][mm] = s; s2B[mt][mm] = s2;
        }
    }
    __syncthreads();
#pragma unroll
    for (int mt = 0; mt < 2; mt++)
#pragma unroll
        for (int mm = 0; mm < 2; mm++) {
            int rloc = wm + mt * 16 + mm * 8 + gid;
            if (tig == 0) {
                stats[((wid >> 1) * 64 + rloc) * 2]     = sB[mt][mm];
                stats[((wid >> 1) * 64 + rloc) * 2 + 1] = s2B[mt][mm];
            }
        }
    __syncthreads();

#pragma unroll
    for (int mt = 0; mt < 2; mt++) {
#pragma unroll
        for (int mm = 0; mm < 2; mm++) {
            int rloc = wm + mt * 16 + mm * 8 + gid;
            int v = m0 + rloc;
            float S = 0.f, S2 = 0.f;
#pragma unroll
            for (int g = 0; g < 4; g++) {
                S  += stats[(g * 64 + rloc) * 2];
                S2 += stats[(g * 64 + rloc) * 2 + 1];
            }
            float mean = S * (1.0f / CDIM);
            float var = S2 * (1.0f / CDIM) - mean * mean;
            float rs = rsqrtf(var + 1e-5f);
#pragma unroll
            for (int nt = 0; nt < 6; nt++) {
                int n = wn + nt * 8 + tig * 2;
                float o0 = (acc[mt][nt][mm * 2]     - mean) * rs * w3[n]     + b3[n];
                float o1 = (acc[mt][nt][mm * 2 + 1] - mean) * rs * w3[n + 1] + b3[n + 1];
                *reinterpret_cast<float2*>(outp + (size_t)v * CDIM + n) = make_float2(o0, o1);
            }
        }
    }
}

// ---------------------------------------------------------------------------
// Single merged weight converter
// ---------------------------------------------------------------------------
__global__ void cvt_all_kernel(const float* __restrict__ ipw,
                               const float* __restrict__ opw,
                               const float* __restrict__ l1w,
                               const float* __restrict__ l2w,
                               __nv_bfloat16* __restrict__ dst) {
    int i = blockIdx.x * blockDim.x + threadIdx.x;
    const int N4 = W16_TOT / 4;
    if (i >= N4) return;
    int e = i * 4;
    const float* src;
    int off;
    if (e < OPW_OFF)      { src = ipw; off = e - IPW_OFF; }
    else if (e < L1W_OFF) { src = opw; off = e - OPW_OFF; }
    else if (e < L2W_OFF) { src = l1w; off = e - L1W_OFF; }
    else                  { src = l2w; off = e - L2W_OFF; }
    float4 v = *reinterpret_cast<const float4*>(src + off);
    reinterpret_cast<__nv_bfloat162*>(dst)[i * 2 + 0] = __floats2bfloat162_rn(v.x, v.y);
    reinterpret_cast<__nv_bfloat162*>(dst)[i * 2 + 1] = __floats2bfloat162_rn(v.z, v.w);
}

// ---------------------------------------------------------------------------
// Prep (coalesced, voxel order): qin16 = bf16(cur+pos); feat16 = bf16(cur)
// ---------------------------------------------------------------------------
__global__ void prep_kernel(const float* __restrict__ cur,
                            const float* __restrict__ pos,
                            __nv_bfloat16* __restrict__ qin,
                            __nv_bfloat16* __restrict__ feat) {
    int gid = blockIdx.x * blockDim.x + threadIdx.x;
    const int TOT = NVOX * (CDIM / 4);
    if (gid >= TOT) return;
    float4 f = reinterpret_cast<const float4*>(cur)[gid];
    float4 pp = reinterpret_cast<const float4*>(pos)[gid];
    __nv_bfloat162* f2 = reinterpret_cast<__nv_bfloat162*>(feat);
    __nv_bfloat162* q2 = reinterpret_cast<__nv_bfloat162*>(qin);
    f2[gid * 2 + 0] = __floats2bfloat162_rn(f.x, f.y);
    f2[gid * 2 + 1] = __floats2bfloat162_rn(f.z, f.w);
    q2[gid * 2 + 0] = __floats2bfloat162_rn(f.x + pp.x, f.y + pp.y);
    q2[gid * 2 + 1] = __floats2bfloat162_rn(f.z + pp.z, f.w + pp.w);
}

// ---------------------------------------------------------------------------
// Attention: one block per set, 288 threads = (36 rows x 8 heads).
// K staged in smem as FP32 (unpacked once at fill); V staged as BF16 (pure
// copy at fill, unpacked at use — V accumulation is ILP-rich so cvt is cheap).
// Q loaded per-thread from global. Q.K dot uses 4 partial accumulators to
// break the serial FFMA chain. smem: 27648 + 13824 = 41.5 KB.
// ---------------------------------------------------------------------------
#define ATTN_SMEM (SETSZ * CDIM * 4 + SETSZ * CDIM * 2 + 160)

__global__ __launch_bounds__(288) void attn_kernel(const __nv_bfloat16* __restrict__ qk,
                                                   const __nv_bfloat16* __restrict__ v,
                                                   const int* __restrict__ inds_all,
                                                   const int* __restrict__ block_id,
                                                   int layer,
                                                   __nv_bfloat16* __restrict__ o) {
    extern __shared__ float smf[];
    float* ks = smf;                                              // 36x192 fp32
    __nv_bfloat16* vs = reinterpret_cast<__nv_bfloat16*>(smf + SETSZ * CDIM);  // 36x192 bf16
    int* vids = reinterpret_cast<int*>(vs + SETSZ * CDIM);

    int s = blockIdx.x;
    int tid = threadIdx.x;

    if (tid < SETSZ) {
        int shift = block_id[0] & 1;
        vids[tid] = inds_all[((size_t)shift * 2 + layer) * NVOX + s * SETSZ + tid];
    }
    __syncthreads();

    const uint4* qk4 = reinterpret_cast<const uint4*>(qk);
    const uint4* v4 = reinterpret_cast<const uint4*>(v);

    // Fill K (qk row chunks 24..47), unpack to fp32
    for (int idx = tid; idx < SETSZ * 24; idx += 288) {
        int row = idx / 24, c = idx % 24;
        uint4 u = qk4[(size_t)vids[row] * 48 + 24 + c];
        float4 lo, hi;
        unpack8_f4(u, lo, hi);
        float* dst = ks + row * CDIM + c * 8;
        reinterpret_cast<float4*>(dst)[0] = lo;
        reinterpret_cast<float4*>(dst)[1] = hi;
    }
    // Fill V: pure uint4 copy (bf16 kept packed)
    for (int idx = tid; idx < SETSZ * 24; idx += 288) {
        int row = idx / 24, c = idx % 24;
        reinterpret_cast<uint4*>(vs)[row * 24 + c] = v4[(size_t)vids[row] * 24 + c];
    }

    int l = tid % SETSZ;
    int h = tid / SETSZ;

    // Per-thread Q row straight from global, pre-scaled
    const float scale = 0.20412414523193154f;
    float qr[DH];
    {
        const uint4* qrow = qk4 + (size_t)vids[l] * 48 + h * 3;
#pragma unroll
        for (int c = 0; c < 3; c++) {
            float4 lo, hi;
            unpack8_f4(qrow[c], lo, hi);
            qr[c * 8 + 0] = lo.x * scale; qr[c * 8 + 1] = lo.y * scale;
            qr[c * 8 + 2] = lo.z * scale; qr[c * 8 + 3] = lo.w * scale;
            qr[c * 8 + 4] = hi.x * scale; qr[c * 8 + 5] = hi.y * scale;
            qr[c * 8 + 6] = hi.z * scale; qr[c * 8 + 7] = hi.w * scale;
        }
    }
    __syncthreads();

    float sc[SETSZ];
    float mx = -1e30f;
#pragma unroll 4
    for (int m = 0; m < SETSZ; m++) {
        const float4* krow = reinterpret_cast<const float4*>(ks + m * CDIM + h * DH);
        // 4 partial accumulators -> 4 independent FFMA chains of depth 6
        float d0 = 0.f, d1 = 0.f, d2 = 0.f, d3 = 0.f;
#pragma unroll
        for (int c = 0; c < 6; c++) {
            float4 t = krow[c];
            d0 += qr[c * 4 + 0] * t.x;
            d1 += qr[c * 4 + 1] * t.y;
            d2 += qr[c * 4 + 2] * t.z;
            d3 += qr[c * 4 + 3] * t.w;
        }
        float dot = (d0 + d1) + (d2 + d3);
        sc[m] = dot;
        mx = fmaxf(mx, dot);
    }
    float sum = 0.f;
#pragma unroll 4
    for (int m = 0; m < SETSZ; m++) {
        sc[m] = expf(sc[m] - mx);
        sum += sc[m];
    }
    float inv = 1.0f / sum;

    float acc[DH];
#pragma unroll
    for (int d = 0; d < DH; d++) acc[d] = 0.f;
#pragma unroll 4
    for (int m = 0; m < SETSZ; m++) {
        const uint4* vrow = reinterpret_cast<const uint4*>(vs + m * CDIM + h * DH);
        float p = sc[m];
#pragma unroll
        for (int c = 0; c < 3; c++) {
            float4 lo, hi;
            unpack8_f4(vrow[c], lo, hi);
            acc[c * 8 + 0] += p * lo.x; acc[c * 8 + 1] += p * lo.y;
            acc[c * 8 + 2] += p * lo.z; acc[c * 8 + 3] += p * lo.w;
            acc[c * 8 + 4] += p * hi.x; acc[c * 8 + 5] += p * hi.y;
            acc[c * 8 + 6] += p * hi.z; acc[c * 8 + 7] += p * hi.w;
        }
    }

    __nv_bfloat162* o2 = reinterpret_cast<__nv_bfloat162*>(
        o + (size_t)s * SETSZ * CDIM + l * CDIM + h * DH);
#pragma unroll
    for (int d2 = 0; d2 < DH / 2; d2++)
        o2[d2] = __floats2bfloat162_rn(acc[d2 * 2] * inv, acc[d2 * 2 + 1] * inv);
}

// ---------------------------------------------------------------------------
// Host orchestration
// ---------------------------------------------------------------------------
extern "C" void kernel_launch(void* const* d_in, const int* in_sizes, int n_in,
                              void* d_out, int out_size) {
    (void)in_sizes; (void)n_in; (void)out_size;
    const float* src  = (const float*)d_in[0];
    const int*   inds = (const int*)d_in[1];
    const float* pos  = (const float*)d_in[3];
    const int*   bid  = (const int*)d_in[4];
    const float* ipw  = (const float*)d_in[5];
    const float* ipb  = (const float*)d_in[6];
    const float* opw  = (const float*)d_in[7];
    const float* opb  = (const float*)d_in[8];
    const float* l1w  = (const float*)d_in[9];
    const float* l1b  = (const float*)d_in[10];
    const float* l2w  = (const float*)d_in[11];
    const float* l2b  = (const float*)d_in[12];
    const float* n1w  = (const float*)d_in[13];
    const float* n1b  = (const float*)d_in[14];
    const float* n2w  = (const float*)d_in[15];
    const float* n2b  = (const float*)d_in[16];
    const float* n3w  = (const float*)d_in[17];
    const float* n3b  = (const float*)d_in[18];

    float* out = (float*)d_out;

    __nv_bfloat16 *qk16, *qin16, *feat16, *v16, *x16, *h16, *w16;
    float *x32;
    cudaGetSymbolAddress((void**)&qk16, g_qk16);
    cudaGetSymbolAddress((void**)&qin16, g_qin16);
    cudaGetSymbolAddress((void**)&feat16, g_feat16);
    cudaGetSymbolAddress((void**)&v16, g_v16);
    cudaGetSymbolAddress((void**)&x16, g_x16);
    cudaGetSymbolAddress((void**)&h16, g_h16);
    cudaGetSymbolAddress((void**)&w16, g_w16);
    cudaGetSymbolAddress((void**)&x32, g_x32);

    cudaFuncSetAttribute((const void*)gemm_bf16_kernel<__nv_bfloat16, true>,
                         cudaFuncAttributeMaxDynamicSharedMemorySize, GEMM_SMEM);
    cudaFuncSetAttribute((const void*)qkv_gemm_kernel,
                         cudaFuncAttributeMaxDynamicSharedMemorySize, GEMM_SMEM);
    cudaFuncSetAttribute((const void*)gemm_op_ln1_kernel,
                         cudaFuncAttributeMaxDynamicSharedMemorySize, FUSED_SMEM);
    cudaFuncSetAttribute((const void*)gemm_ffn_ln23_kernel,
                         cudaFuncAttributeMaxDynamicSharedMemorySize, FUSED_SMEM);
    cudaFuncSetAttribute((const void*)attn_kernel,
                         cudaFuncAttributeMaxDynamicSharedMemorySize, ATTN_SMEM);

    cvt_all_kernel<<<(W16_TOT / 4 + 255) / 256, 256>>>(ipw, opw, l1w, l2w, w16);

    const int TOT4 = NVOX * (CDIM / 4);
    dim3 pgrid((TOT4 + 255) / 256);
    dim3 gridQKV(9, NVOX / 256);
    dim3 grid768(DFF / 64, NVOX / 256);
    dim3 fgrid(NVOX / 64);

    for (int i = 0; i < 2; i++) {
        const __nv_bfloat16* Wqkv = w16 + IPW_OFF + (size_t)i * 3 * CDIM * CDIM;
        const float* bqkv = ipb + (size_t)i * 3 * CDIM;
        const float* posL = pos + (size_t)i * NVOX * CDIM;
        const float* cur = (i == 0) ? src : out;

        prep_kernel<<<pgrid, 256>>>(cur, posL, qin16, feat16);

        qkv_gemm_kernel<<<gridQKV, 256, GEMM_SMEM>>>(
            qin16, feat16, Wqkv, bqkv, qk16, v16);

        attn_kernel<<<NSET, 288, ATTN_SMEM>>>(qk16, v16, inds, bid, i, qin16);

        gemm_op_ln1_kernel<<<fgrid, 256, FUSED_SMEM>>>(
            qin16, w16 + OPW_OFF + (size_t)i * CDIM * CDIM, opb + (size_t)i * CDIM,
            cur, inds, bid, i, n1w + i * CDIM, n1b + i * CDIM, x32, x16);

        gemm_bf16_kernel<__nv_bfloat16, true><<<grid768, 256, GEMM_SMEM>>>(
            x16, w16 + L1W_OFF + (size_t)i * DFF * CDIM, l1b + (size_t)i * DFF,
            h16, CDIM, DFF);

        gemm_ffn_ln23_kernel<<<fgrid, 256, FUSED_SMEM>>>(
            h16, w16 + L2W_OFF + (size_t)i * CDIM * DFF, l2b + (size_t)i * CDIM,
            x32, cur, n2w + i * CDIM, n2b + i * CDIM,
            n3w + i * CDIM, n3b + i * CDIM, out);
    }
}

// round 14
// speedup vs baseline: 1.0747x; 1.0071x over previous
#include <cuda_runtime.h>
#include <cuda_bf16.h>
#include <math.h>
#include <stdint.h>

// Problem constants
#define NVOX 147456
#define CDIM 192
#define NH 8
#define DH 24
#define DFF 768
#define SETSZ 36
#define NSET 4096

// ---------------------------------------------------------------------------
// Scratch (device globals)
// ---------------------------------------------------------------------------
__device__ __nv_bfloat16 g_qk16[(size_t)NVOX * 2 * CDIM];  // Q|K voxel-order (stride 384)
__device__ __nv_bfloat16 g_qin16[(size_t)NVOX * CDIM];     // q_in (voxel) / attn out (set)
__device__ __nv_bfloat16 g_feat16[(size_t)NVOX * CDIM];    // bf16(cur), voxel order
__device__ __nv_bfloat16 g_v16[(size_t)NVOX * CDIM];       // V, voxel order
__device__ __nv_bfloat16 g_x16[(size_t)NVOX * CDIM];
__device__ __nv_bfloat16 g_h16[(size_t)NVOX * DFF];
__device__ float g_x32[(size_t)NVOX * CDIM];   // post-LN1 x (fp32)
// bf16 weights: [ipw | opw | l1w | l2w]
#define IPW_OFF 0
#define OPW_OFF 221184
#define L1W_OFF 294912
#define L2W_OFF 589824
#define W16_TOT 884736
__device__ __nv_bfloat16 g_w16[W16_TOT];

// ---------------------------------------------------------------------------
// mma.sync helpers
// ---------------------------------------------------------------------------
__device__ __forceinline__ void cp16(uint32_t dst, const void* src) {
    asm volatile("cp.async.cg.shared.global [%0], [%1], 16;\n" :: "r"(dst), "l"(src));
}
__device__ __forceinline__ void ldsm4(uint32_t* r, uint32_t addr) {
    asm volatile("ldmatrix.sync.aligned.m8n8.x4.shared.b16 {%0,%1,%2,%3}, [%4];"
                 : "=r"(r[0]), "=r"(r[1]), "=r"(r[2]), "=r"(r[3]) : "r"(addr));
}
__device__ __forceinline__ void mma_bf16(float* c, const uint32_t* a, const uint32_t* b) {
    asm volatile(
        "mma.sync.aligned.m16n8k16.row.col.f32.bf16.bf16.f32 "
        "{%0,%1,%2,%3},{%4,%5,%6,%7},{%8,%9},{%0,%1,%2,%3};"
        : "+f"(c[0]), "+f"(c[1]), "+f"(c[2]), "+f"(c[3])
        : "r"(a[0]), "r"(a[1]), "r"(a[2]), "r"(a[3]), "r"(b[0]), "r"(b[1]));
}
// Last chunk waits for its OWN group (wait_group 0); earlier leave prefetch in flight.
__device__ __forceinline__ void cp_wait(bool last) {
    if (last) asm volatile("cp.async.wait_group 0;" ::: "memory");
    else      asm volatile("cp.async.wait_group 1;" ::: "memory");
}
// Unpack 8 bf16 (uint4) -> two float4
__device__ __forceinline__ void unpack8_f4(uint4 u, float4& lo, float4& hi) {
    uint32_t w[4] = {u.x, u.y, u.z, u.w};
    float2 t0 = __bfloat1622float2(*reinterpret_cast<__nv_bfloat162*>(&w[0]));
    float2 t1 = __bfloat1622float2(*reinterpret_cast<__nv_bfloat162*>(&w[1]));
    float2 t2 = __bfloat1622float2(*reinterpret_cast<__nv_bfloat162*>(&w[2]));
    float2 t3 = __bfloat1622float2(*reinterpret_cast<__nv_bfloat162*>(&w[3]));
    lo = make_float4(t0.x, t0.y, t1.x, t1.y);
    hi = make_float4(t2.x, t2.y, t3.x, t3.y);
}

// ---------------------------------------------------------------------------
// Plain GEMM mainloop body (tile 256x64x32, 8 warps 4m x 2n, 3-stage).
// ---------------------------------------------------------------------------
#define GA_STAGE 16384
#define GB_STAGE 4096
#define GB_BASE  (3 * GA_STAGE)
#define GEMM_SMEM (3 * GA_STAGE + 3 * GB_STAGE)  // 61440

#define PLAIN_MAINLOOP(Aptr, Wptr, Kval)                                          \
    float acc[4][4][4];                                                           \
    _Pragma("unroll")                                                             \
    for (int mt = 0; mt < 4; mt++)                                                \
        _Pragma("unroll")                                                         \
        for (int nt = 0; nt < 4; nt++)                                            \
            _Pragma("unroll")                                                     \
            for (int r = 0; r < 4; r++) acc[mt][nt][r] = 0.f;                     \
    auto stage = [&](int kt, int buf) {                                           \
        const int k0 = kt * 32;                                                   \
        const uint32_t aB = sbase + buf * GA_STAGE;                               \
        const uint32_t bB = sbase + GB_BASE + buf * GB_STAGE;                     \
        _Pragma("unroll")                                                         \
        for (int i = 0; i < 4; i++) {                                             \
            int idx = i * 256 + tid;                                              \
            int row = idx >> 2, ch = idx & 3;                                     \
            cp16(aB + row * 64 + ((ch ^ ((row >> 1) & 3)) * 16),                  \
                 (Aptr) + (size_t)(m0 + row) * (Kval) + k0 + ch * 8);             \
        }                                                                         \
        {                                                                         \
            int row = tid >> 2, ch = tid & 3;                                     \
            cp16(bB + row * 64 + ((ch ^ ((row >> 1) & 3)) * 16),                  \
                 (Wptr) + (size_t)(n0 + row) * (Kval) + k0 + ch * 8);             \
        }                                                                         \
        asm volatile("cp.async.commit_group;" ::: "memory");                      \
    };                                                                            \
    const int nk = (Kval) >> 5;                                                   \
    stage(0, 0);                                                                  \
    stage(1, 1);                                                                  \
    for (int t = 0; t < nk; t++) {                                                \
        const int buf = t % 3;                                                    \
        cp_wait(t == nk - 1);                                                     \
        __syncthreads();                                                          \
        const uint32_t aB = sbase + buf * GA_STAGE;                               \
        const uint32_t bB = sbase + GB_BASE + buf * GB_STAGE;                     \
        _Pragma("unroll")                                                         \
        for (int ks = 0; ks < 2; ks++) {                                          \
            uint32_t af[4][4], bf[4][2];                                          \
            _Pragma("unroll")                                                     \
            for (int mt = 0; mt < 4; mt++) {                                      \
                int row = wm + mt * 16 + (lane & 15);                             \
                int ch = ks * 2 + (lane >> 4);                                    \
                ldsm4(af[mt], aB + row * 64 + ((ch ^ ((row >> 1) & 3)) * 16));    \
            }                                                                     \
            _Pragma("unroll")                                                     \
            for (int p = 0; p < 2; p++) {                                         \
                int row = wn + p * 16 + ((lane >> 4) << 3) + (lane & 7);          \
                int ch = ks * 2 + ((lane >> 3) & 1);                              \
                uint32_t r4[4];                                                   \
                ldsm4(r4, bB + row * 64 + ((ch ^ ((row >> 1) & 3)) * 16));        \
                bf[p * 2 + 0][0] = r4[0]; bf[p * 2 + 0][1] = r4[1];               \
                bf[p * 2 + 1][0] = r4[2]; bf[p * 2 + 1][1] = r4[3];               \
            }                                                                     \
            _Pragma("unroll")                                                     \
            for (int mt = 0; mt < 4; mt++)                                        \
                _Pragma("unroll")                                                 \
                for (int nt = 0; nt < 4; nt++)                                    \
                    mma_bf16(acc[mt][nt], af[mt], bf[nt]);                        \
        }                                                                         \
        __syncthreads();                                                          \
        if (t + 2 < nk) stage(t + 2, (t + 2) % 3);                                \
    }

// ---------------------------------------------------------------------------
// Plain bf16 GEMM (lin1): D[M,Nc] = A @ W^T + bias (opt ReLU)
// ---------------------------------------------------------------------------
template <typename OutT, bool RELU>
__global__ __launch_bounds__(256) void gemm_bf16_kernel(
        const __nv_bfloat16* __restrict__ A,
        const __nv_bfloat16* __restrict__ W,
        const float* __restrict__ bias,
        OutT* __restrict__ D,
        int K, int Nc) {
    extern __shared__ unsigned char smem[];
    const uint32_t sbase = (uint32_t)__cvta_generic_to_shared(smem);
    const int tid = threadIdx.x;
    const int lane = tid & 31;
    const int wid = tid >> 5;
    const int wm = (wid & 3) * 64;
    const int wn = (wid >> 2) * 32;
    const int m0 = blockIdx.y * 256;
    const int n0 = blockIdx.x * 64;

    PLAIN_MAINLOOP(A, W, K)

#pragma unroll
    for (int mt = 0; mt < 4; mt++) {
#pragma unroll
        for (int nt = 0; nt < 4; nt++) {
            int m = m0 + wm + mt * 16 + (lane >> 2);
            int n = n0 + wn + nt * 8 + (lane & 3) * 2;
            float b0 = bias[n], b1 = bias[n + 1];
            float v0 = acc[mt][nt][0] + b0;
            float v1 = acc[mt][nt][1] + b1;
            float v2 = acc[mt][nt][2] + b0;
            float v3 = acc[mt][nt][3] + b1;
            if (RELU) {
                v0 = fmaxf(v0, 0.f); v1 = fmaxf(v1, 0.f);
                v2 = fmaxf(v2, 0.f); v3 = fmaxf(v3, 0.f);
            }
            if constexpr (sizeof(OutT) == 2) {
                *reinterpret_cast<__nv_bfloat162*>((__nv_bfloat16*)D + (size_t)m * Nc + n) =
                    __floats2bfloat162_rn(v0, v1);
                *reinterpret_cast<__nv_bfloat162*>((__nv_bfloat16*)D + (size_t)(m + 8) * Nc + n) =
                    __floats2bfloat162_rn(v2, v3);
            } else {
                *reinterpret_cast<float2*>((float*)D + (size_t)m * Nc + n) = make_float2(v0, v1);
                *reinterpret_cast<float2*>((float*)D + (size_t)(m + 8) * Nc + n) = make_float2(v2, v3);
            }
        }
    }
}

// ---------------------------------------------------------------------------
// Merged QKV GEMM: Nc spans 576 (Wq|Wk|Wv rows contiguous).
// ---------------------------------------------------------------------------
__global__ __launch_bounds__(256) void qkv_gemm_kernel(
        const __nv_bfloat16* __restrict__ Aq,
        const __nv_bfloat16* __restrict__ Af,
        const __nv_bfloat16* __restrict__ W,
        const float* __restrict__ bias,
        __nv_bfloat16* __restrict__ Dqk,
        __nv_bfloat16* __restrict__ Dv) {
    extern __shared__ unsigned char smem[];
    const uint32_t sbase = (uint32_t)__cvta_generic_to_shared(smem);
    const int tid = threadIdx.x;
    const int lane = tid & 31;
    const int wid = tid >> 5;
    const int wm = (wid & 3) * 64;
    const int wn = (wid >> 2) * 32;
    const int m0 = blockIdx.y * 256;
    const int n0 = blockIdx.x * 64;

    const bool isV = (n0 >= 2 * CDIM);
    const __nv_bfloat16* A = isV ? Af : Aq;
    __nv_bfloat16* D = isV ? Dv : Dqk;
    const int dStride = isV ? CDIM : 2 * CDIM;
    const int dCol0 = isV ? n0 - 2 * CDIM : n0;

    PLAIN_MAINLOOP(A, W, CDIM)

#pragma unroll
    for (int mt = 0; mt < 4; mt++) {
#pragma unroll
        for (int nt = 0; nt < 4; nt++) {
            int m = m0 + wm + mt * 16 + (lane >> 2);
            int nl = wn + nt * 8 + (lane & 3) * 2;
            int n = n0 + nl;
            float b0 = bias[n], b1 = bias[n + 1];
            int nd = dCol0 + nl;
            *reinterpret_cast<__nv_bfloat162*>(D + (size_t)m * dStride + nd) =
                __floats2bfloat162_rn(acc[mt][nt][0] + b0, acc[mt][nt][1] + b1);
            *reinterpret_cast<__nv_bfloat162*>(D + (size_t)(m + 8) * dStride + nd) =
                __floats2bfloat162_rn(acc[mt][nt][2] + b0, acc[mt][nt][3] + b1);
        }
    }
}

// ---------------------------------------------------------------------------
// Fused GEMM mainloop config (tile 64 x 192, K chunks of 32, 3-stage).
// ---------------------------------------------------------------------------
#define FA_STAGE 4096
#define FB_STAGE 12288
#define FB_BASE  (3 * FA_STAGE)
#define FUSED_SMEM (3 * FA_STAGE + 3 * FB_STAGE)  // 49152

#define FUSED_MAINLOOP(Aptr, Wptr, Kval)                                              \
    float acc[2][6][4];                                                               \
    _Pragma("unroll")                                                                 \
    for (int mt = 0; mt < 2; mt++)                                                    \
        _Pragma("unroll")                                                             \
        for (int nt = 0; nt < 6; nt++)                                                \
            _Pragma("unroll")                                                         \
            for (int r = 0; r < 4; r++) acc[mt][nt][r] = 0.f;                         \
    auto stage = [&](int kt, int buf) {                                               \
        const int k0 = kt * 32;                                                       \
        {                                                                             \
            int row = tid >> 2, ch = tid & 3;                                         \
            cp16(sbase + buf * FA_STAGE + row * 64 + ((ch ^ ((row >> 1) & 3)) * 16),  \
                 (Aptr) + (size_t)(m0 + row) * (Kval) + k0 + ch * 8);                 \
        }                                                                             \
        _Pragma("unroll")                                                             \
        for (int i = 0; i < 3; i++) {                                                 \
            int idx = i * 256 + tid;                                                  \
            int row = idx >> 2, ch = idx & 3;                                         \
            cp16(sbase + FB_BASE + buf * FB_STAGE + row * 64 +                        \
                     ((ch ^ ((row >> 1) & 3)) * 16),                                  \
                 (Wptr) + (size_t)row * (Kval) + k0 + ch * 8);                        \
        }                                                                             \
        asm volatile("cp.async.commit_group;" ::: "memory");                          \
    };                                                                                \
    const int nk = (Kval) >> 5;                                                       \
    stage(0, 0);                                                                      \
    stage(1, 1);                                                                      \
    for (int t = 0; t < nk; t++) {                                                    \
        const int buf = t % 3;                                                        \
        cp_wait(t == nk - 1);                                                         \
        __syncthreads();                                                              \
        const uint32_t aB = sbase + buf * FA_STAGE;                                   \
        const uint32_t bB = sbase + FB_BASE + buf * FB_STAGE;                         \
        _Pragma("unroll")                                                             \
        for (int ks = 0; ks < 2; ks++) {                                              \
            uint32_t af[2][4], bf[6][2];                                              \
            _Pragma("unroll")                                                         \
            for (int mt = 0; mt < 2; mt++) {                                          \
                int row = wm + mt * 16 + (lane & 15);                                 \
                int ch = ks * 2 + (lane >> 4);                                        \
                ldsm4(af[mt], aB + row * 64 + ((ch ^ ((row >> 1) & 3)) * 16));        \
            }                                                                         \
            _Pragma("unroll")                                                         \
            for (int p = 0; p < 3; p++) {                                             \
                int row = wn + p * 16 + ((lane >> 4) << 3) + (lane & 7);              \
                int ch = ks * 2 + ((lane >> 3) & 1);                                  \
                uint32_t r4[4];                                                       \
                ldsm4(r4, bB + row * 64 + ((ch ^ ((row >> 1) & 3)) * 16));            \
                bf[p * 2 + 0][0] = r4[0]; bf[p * 2 + 0][1] = r4[1];                   \
                bf[p * 2 + 1][0] = r4[2]; bf[p * 2 + 1][1] = r4[3];                   \
            }                                                                         \
            _Pragma("unroll")                                                         \
            for (int mt = 0; mt < 2; mt++)                                            \
                _Pragma("unroll")                                                     \
                for (int nt = 0; nt < 6; nt++)                                        \
                    mma_bf16(acc[mt][nt], af[mt], bf[nt]);                            \
        }                                                                             \
        __syncthreads();                                                              \
        if (t + 2 < nk) stage(t + 2, (t + 2) % 3);                                    \
    }

// ---------------------------------------------------------------------------
// Fused out_proj + scatter + residual + LN1.
// ---------------------------------------------------------------------------
__global__ __launch_bounds__(256) void gemm_op_ln1_kernel(
        const __nv_bfloat16* __restrict__ A,
        const __nv_bfloat16* __restrict__ W,
        const float* __restrict__ bias,
        const float* __restrict__ cur,
        const int* __restrict__ inds_all, const int* __restrict__ block_id, int layer,
        const float* __restrict__ lnw, const float* __restrict__ lnb,
        float* __restrict__ x32, __nv_bfloat16* __restrict__ x16) {
    extern __shared__ unsigned char smem[];
    const uint32_t sbase = (uint32_t)__cvta_generic_to_shared(smem);
    const int tid = threadIdx.x;
    const int lane = tid & 31;
    const int wid = tid >> 5;
    const int wm = (wid & 1) * 32;
    const int wn = (wid >> 1) * 48;
    const int m0 = blockIdx.x * 64;

    FUSED_MAINLOOP(A, W, CDIM)

    float* stats = reinterpret_cast<float*>(smem);
    const int gid = lane >> 2, tig = lane & 3;
    const int shift = block_id[0] & 1;
    const int* ip = inds_all + ((size_t)shift * 2 + layer) * NVOX;
    int vrow[2][2];
#pragma unroll
    for (int mt = 0; mt < 2; mt++) {
#pragma unroll
        for (int mm = 0; mm < 2; mm++) {
            int rloc = wm + mt * 16 + mm * 8 + gid;
            int v = ip[m0 + rloc];
            vrow[mt][mm] = v;
            float s = 0.f, s2 = 0.f;
#pragma unroll
            for (int nt = 0; nt < 6; nt++) {
                int n = wn + nt * 8 + tig * 2;
                float2 c = *reinterpret_cast<const float2*>(cur + (size_t)v * CDIM + n);
                float a0 = acc[mt][nt][mm * 2]     + bias[n]     + c.x;
                float a1 = acc[mt][nt][mm * 2 + 1] + bias[n + 1] + c.y;
                acc[mt][nt][mm * 2] = a0; acc[mt][nt][mm * 2 + 1] = a1;
                s += a0 + a1; s2 += a0 * a0 + a1 * a1;
            }
            s  += __shfl_xor_sync(0xffffffffu, s, 1);  s  += __shfl_xor_sync(0xffffffffu, s, 2);
            s2 += __shfl_xor_sync(0xffffffffu, s2, 1); s2 += __shfl_xor_sync(0xffffffffu, s2, 2);
            if (tig == 0) {
                stats[((wid >> 1) * 64 + rloc) * 2]     = s;
                stats[((wid >> 1) * 64 + rloc) * 2 + 1] = s2;
            }
        }
    }
    __syncthreads();
#pragma unroll
    for (int mt = 0; mt < 2; mt++) {
#pragma unroll
        for (int mm = 0; mm < 2; mm++) {
            int rloc = wm + mt * 16 + mm * 8 + gid;
            int v = vrow[mt][mm];
            float S = 0.f, S2 = 0.f;
#pragma unroll
            for (int g = 0; g < 4; g++) {
                S  += stats[(g * 64 + rloc) * 2];
                S2 += stats[(g * 64 + rloc) * 2 + 1];
            }
            float mean = S * (1.0f / CDIM);
            float var = S2 * (1.0f / CDIM) - mean * mean;
            float rs = rsqrtf(var + 1e-5f);
#pragma unroll
            for (int nt = 0; nt < 6; nt++) {
                int n = wn + nt * 8 + tig * 2;
                float o0 = (acc[mt][nt][mm * 2]     - mean) * rs * lnw[n]     + lnb[n];
                float o1 = (acc[mt][nt][mm * 2 + 1] - mean) * rs * lnw[n + 1] + lnb[n + 1];
                *reinterpret_cast<float2*>(x32 + (size_t)v * CDIM + n) = make_float2(o0, o1);
                *reinterpret_cast<__nv_bfloat162*>(x16 + (size_t)v * CDIM + n) =
                    __floats2bfloat162_rn(o0, o1);
            }
        }
    }
}

// ---------------------------------------------------------------------------
// Fused lin2 + LN2 + LN3 (voxel-order rows). Optionally also emits next
// layer's prep outputs: qinN = bf16(out + posN), featN = bf16(out).
// ---------------------------------------------------------------------------
__global__ __launch_bounds__(256) void gemm_ffn_ln23_kernel(
        const __nv_bfloat16* __restrict__ A,
        const __nv_bfloat16* __restrict__ W,
        const float* __restrict__ bias,
        const float* __restrict__ x32,
        const float* __restrict__ cur,
        const float* __restrict__ w2, const float* __restrict__ b2,
        const float* __restrict__ w3, const float* __restrict__ b3,
        float* __restrict__ outp,
        const float* __restrict__ posN,
        __nv_bfloat16* __restrict__ qinN,
        __nv_bfloat16* __restrict__ featN) {
    extern __shared__ unsigned char smem[];
    const uint32_t sbase = (uint32_t)__cvta_generic_to_shared(smem);
    const int tid = threadIdx.x;
    const int lane = tid & 31;
    const int wid = tid >> 5;
    const int wm = (wid & 1) * 32;
    const int wn = (wid >> 1) * 48;
    const int m0 = blockIdx.x * 64;

    FUSED_MAINLOOP(A, W, DFF)

    float* stats = reinterpret_cast<float*>(smem);
    const int gid = lane >> 2, tig = lane & 3;

#pragma unroll
    for (int mt = 0; mt < 2; mt++) {
#pragma unroll
        for (int mm = 0; mm < 2; mm++) {
            int rloc = wm + mt * 16 + mm * 8 + gid;
            int v = m0 + rloc;
            float s = 0.f, s2 = 0.f;
#pragma unroll
            for (int nt = 0; nt < 6; nt++) {
                int n = wn + nt * 8 + tig * 2;
                float2 xr = *reinterpret_cast<const float2*>(x32 + (size_t)v * CDIM + n);
                float a0 = acc[mt][nt][mm * 2]     + bias[n]     + xr.x;
                float a1 = acc[mt][nt][mm * 2 + 1] + bias[n + 1] + xr.y;
                acc[mt][nt][mm * 2] = a0; acc[mt][nt][mm * 2 + 1] = a1;
                s += a0 + a1; s2 += a0 * a0 + a1 * a1;
            }
            s  += __shfl_xor_sync(0xffffffffu, s, 1);  s  += __shfl_xor_sync(0xffffffffu, s, 2);
            s2 += __shfl_xor_sync(0xffffffffu, s2, 1); s2 += __shfl_xor_sync(0xffffffffu, s2, 2);
            if (tig == 0) {
                stats[((wid >> 1) * 64 + rloc) * 2]     = s;
                stats[((wid >> 1) * 64 + rloc) * 2 + 1] = s2;
            }
        }
    }
    __syncthreads();

    float sB[2][2], s2B[2][2];
#pragma unroll
    for (int mt = 0; mt < 2; mt++) {
#pragma unroll
        for (int mm = 0; mm < 2; mm++) {
            int rloc = wm + mt * 16 + mm * 8 + gid;
            int v = m0 + rloc;
            float S = 0.f, S2 = 0.f;
#pragma unroll
            for (int g = 0; g < 4; g++) {
                S  += stats[(g * 64 + rloc) * 2];
                S2 += stats[(g * 64 + rloc) * 2 + 1];
            }
            float mean = S * (1.0f / CDIM);
            float var = S2 * (1.0f / CDIM) - mean * mean;
            float rs = rsqrtf(var + 1e-5f);
            float s = 0.f, s2 = 0.f;
#pragma unroll
            for (int nt = 0; nt < 6; nt++) {
                int n = wn + nt * 8 + tig * 2;
                float2 cv = *reinterpret_cast<const float2*>(cur + (size_t)v * CDIM + n);
                float t0 = (acc[mt][nt][mm * 2]     - mean) * rs * w2[n]     + b2[n]     + cv.x;
                float t1 = (acc[mt][nt][mm * 2 + 1] - mean) * rs * w2[n + 1] + b2[n + 1] + cv.y;
                acc[mt][nt][mm * 2] = t0; acc[mt][nt][mm * 2 + 1] = t1;
                s += t0 + t1; s2 += t0 * t0 + t1 * t1;
            }
            s  += __shfl_xor_sync(0xffffffffu, s, 1);  s  += __shfl_xor_sync(0xffffffffu, s, 2);
            s2 += __shfl_xor_sync(0xffffffffu, s2, 1); s2 += __shfl_xor_sync(0xffffffffu, s2, 2);
            sB[mt][mm] = s; s2B[mt][mm] = s2;
        }
    }
    __syncthreads();
#pragma unroll
    for (int mt = 0; mt < 2; mt++)
#pragma unroll
        for (int mm = 0; mm < 2; mm++) {
            int rloc = wm + mt * 16 + mm * 8 + gid;
            if (tig == 0) {
                stats[((wid >> 1) * 64 + rloc) * 2]     = sB[mt][mm];
                stats[((wid >> 1) * 64 + rloc) * 2 + 1] = s2B[mt][mm];
            }
        }
    __syncthreads();

#pragma unroll
    for (int mt = 0; mt < 2; mt++) {
#pragma unroll
        for (int mm = 0; mm < 2; mm++) {
            int rloc = wm + mt * 16 + mm * 8 + gid;
            int v = m0 + rloc;
            float S = 0.f, S2 = 0.f;
#pragma unroll
            for (int g = 0; g < 4; g++) {
                S  += stats[(g * 64 + rloc) * 2];
                S2 += stats[(g * 64 + rloc) * 2 + 1];
            }
            float mean = S * (1.0f / CDIM);
            float var = S2 * (1.0f / CDIM) - mean * mean;
            float rs = rsqrtf(var + 1e-5f);
#pragma unroll
            for (int nt = 0; nt < 6; nt++) {
                int n = wn + nt * 8 + tig * 2;
                float o0 = (acc[mt][nt][mm * 2]     - mean) * rs * w3[n]     + b3[n];
                float o1 = (acc[mt][nt][mm * 2 + 1] - mean) * rs * w3[n + 1] + b3[n + 1];
                *reinterpret_cast<float2*>(outp + (size_t)v * CDIM + n) = make_float2(o0, o1);
                if (qinN) {
                    float2 pp = *reinterpret_cast<const float2*>(posN + (size_t)v * CDIM + n);
                    *reinterpret_cast<__nv_bfloat162*>(featN + (size_t)v * CDIM + n) =
                        __floats2bfloat162_rn(o0, o1);
                    *reinterpret_cast<__nv_bfloat162*>(qinN + (size_t)v * CDIM + n) =
                        __floats2bfloat162_rn(o0 + pp.x, o1 + pp.y);
                }
            }
        }
    }
}

// ---------------------------------------------------------------------------
// Single merged weight converter
// ---------------------------------------------------------------------------
__global__ void cvt_all_kernel(const float* __restrict__ ipw,
                               const float* __restrict__ opw,
                               const float* __restrict__ l1w,
                               const float* __restrict__ l2w,
                               __nv_bfloat16* __restrict__ dst) {
    int i = blockIdx.x * blockDim.x + threadIdx.x;
    const int N4 = W16_TOT / 4;
    if (i >= N4) return;
    int e = i * 4;
    const float* src;
    int off;
    if (e < OPW_OFF)      { src = ipw; off = e - IPW_OFF; }
    else if (e < L1W_OFF) { src = opw; off = e - OPW_OFF; }
    else if (e < L2W_OFF) { src = l1w; off = e - L1W_OFF; }
    else                  { src = l2w; off = e - L2W_OFF; }
    float4 v = *reinterpret_cast<const float4*>(src + off);
    reinterpret_cast<__nv_bfloat162*>(dst)[i * 2 + 0] = __floats2bfloat162_rn(v.x, v.y);
    reinterpret_cast<__nv_bfloat162*>(dst)[i * 2 + 1] = __floats2bfloat162_rn(v.z, v.w);
}

// ---------------------------------------------------------------------------
// Prep (coalesced, voxel order): qin16 = bf16(cur+pos); feat16 = bf16(cur)
// ---------------------------------------------------------------------------
__global__ void prep_kernel(const float* __restrict__ cur,
                            const float* __restrict__ pos,
                            __nv_bfloat16* __restrict__ qin,
                            __nv_bfloat16* __restrict__ feat) {
    int gid = blockIdx.x * blockDim.x + threadIdx.x;
    const int TOT = NVOX * (CDIM / 4);
    if (gid >= TOT) return;
    float4 f = reinterpret_cast<const float4*>(cur)[gid];
    float4 pp = reinterpret_cast<const float4*>(pos)[gid];
    __nv_bfloat162* f2 = reinterpret_cast<__nv_bfloat162*>(feat);
    __nv_bfloat162* q2 = reinterpret_cast<__nv_bfloat162*>(qin);
    f2[gid * 2 + 0] = __floats2bfloat162_rn(f.x, f.y);
    f2[gid * 2 + 1] = __floats2bfloat162_rn(f.z, f.w);
    q2[gid * 2 + 0] = __floats2bfloat162_rn(f.x + pp.x, f.y + pp.y);
    q2[gid * 2 + 1] = __floats2bfloat162_rn(f.z + pp.z, f.w + pp.w);
}

// ---------------------------------------------------------------------------
// Attention: one block per set, 288 threads = (36 rows x 8 heads).
// K fp32 smem (unpacked at fill); V bf16 smem; Q per-thread from global.
// __expf for hardware MUFU.EX2 softmax.
// ---------------------------------------------------------------------------
#define ATTN_SMEM (SETSZ * CDIM * 4 + SETSZ * CDIM * 2 + 160)

__global__ __launch_bounds__(288) void attn_kernel(const __nv_bfloat16* __restrict__ qk,
                                                   const __nv_bfloat16* __restrict__ v,
                                                   const int* __restrict__ inds_all,
                                                   const int* __restrict__ block_id,
                                                   int layer,
                                                   __nv_bfloat16* __restrict__ o) {
    extern __shared__ float smf[];
    float* ks = smf;                                              // 36x192 fp32
    __nv_bfloat16* vs = reinterpret_cast<__nv_bfloat16*>(smf + SETSZ * CDIM);  // 36x192 bf16
    int* vids = reinterpret_cast<int*>(vs + SETSZ * CDIM);

    int s = blockIdx.x;
    int tid = threadIdx.x;

    if (tid < SETSZ) {
        int shift = block_id[0] & 1;
        vids[tid] = inds_all[((size_t)shift * 2 + layer) * NVOX + s * SETSZ + tid];
    }
    __syncthreads();

    const uint4* qk4 = reinterpret_cast<const uint4*>(qk);
    const uint4* v4 = reinterpret_cast<const uint4*>(v);

    for (int idx = tid; idx < SETSZ * 24; idx += 288) {
        int row = idx / 24, c = idx % 24;
        uint4 u = qk4[(size_t)vids[row] * 48 + 24 + c];
        float4 lo, hi;
        unpack8_f4(u, lo, hi);
        float* dst = ks + row * CDIM + c * 8;
        reinterpret_cast<float4*>(dst)[0] = lo;
        reinterpret_cast<float4*>(dst)[1] = hi;
    }
    for (int idx = tid; idx < SETSZ * 24; idx += 288) {
        int row = idx / 24, c = idx % 24;
        reinterpret_cast<uint4*>(vs)[row * 24 + c] = v4[(size_t)vids[row] * 24 + c];
    }

    int l = tid % SETSZ;
    int h = tid / SETSZ;

    const float scale = 0.20412414523193154f;
    float qr[DH];
    {
        const uint4* qrow = qk4 + (size_t)vids[l] * 48 + h * 3;
#pragma unroll
        for (int c = 0; c < 3; c++) {
            float4 lo, hi;
            unpack8_f4(qrow[c], lo, hi);
            qr[c * 8 + 0] = lo.x * scale; qr[c * 8 + 1] = lo.y * scale;
            qr[c * 8 + 2] = lo.z * scale; qr[c * 8 + 3] = lo.w * scale;
            qr[c * 8 + 4] = hi.x * scale; qr[c * 8 + 5] = hi.y * scale;
            qr[c * 8 + 6] = hi.z * scale; qr[c * 8 + 7] = hi.w * scale;
        }
    }
    __syncthreads();

    float sc[SETSZ];
    float mx = -1e30f;
#pragma unroll 4
    for (int m = 0; m < SETSZ; m++) {
        const float4* krow = reinterpret_cast<const float4*>(ks + m * CDIM + h * DH);
        float d0 = 0.f, d1 = 0.f, d2 = 0.f, d3 = 0.f;
#pragma unroll
        for (int c = 0; c < 6; c++) {
            float4 t = krow[c];
            d0 += qr[c * 4 + 0] * t.x;
            d1 += qr[c * 4 + 1] * t.y;
            d2 += qr[c * 4 + 2] * t.z;
            d3 += qr[c * 4 + 3] * t.w;
        }
        float dot = (d0 + d1) + (d2 + d3);
        sc[m] = dot;
        mx = fmaxf(mx, dot);
    }
    float sum = 0.f;
#pragma unroll 4
    for (int m = 0; m < SETSZ; m++) {
        sc[m] = __expf(sc[m] - mx);
        sum += sc[m];
    }
    float inv = 1.0f / sum;

    float acc[DH];
#pragma unroll
    for (int d = 0; d < DH; d++) acc[d] = 0.f;
#pragma unroll 4
    for (int m = 0; m < SETSZ; m++) {
        const uint4* vrow = reinterpret_cast<const uint4*>(vs + m * CDIM + h * DH);
        float p = sc[m];
#pragma unroll
        for (int c = 0; c < 3; c++) {
            float4 lo, hi;
            unpack8_f4(vrow[c], lo, hi);
            acc[c * 8 + 0] += p * lo.x; acc[c * 8 + 1] += p * lo.y;
            acc[c * 8 + 2] += p * lo.z; acc[c * 8 + 3] += p * lo.w;
            acc[c * 8 + 4] += p * hi.x; acc[c * 8 + 5] += p * hi.y;
            acc[c * 8 + 6] += p * hi.z; acc[c * 8 + 7] += p * hi.w;
        }
    }

    __nv_bfloat162* o2 = reinterpret_cast<__nv_bfloat162*>(
        o + (size_t)s * SETSZ * CDIM + l * CDIM + h * DH);
#pragma unroll
    for (int d2 = 0; d2 < DH / 2; d2++)
        o2[d2] = __floats2bfloat162_rn(acc[d2 * 2] * inv, acc[d2 * 2 + 1] * inv);
}

// ---------------------------------------------------------------------------
// Host orchestration
// ---------------------------------------------------------------------------
extern "C" void kernel_launch(void* const* d_in, const int* in_sizes, int n_in,
                              void* d_out, int out_size) {
    (void)in_sizes; (void)n_in; (void)out_size;
    const float* src  = (const float*)d_in[0];
    const int*   inds = (const int*)d_in[1];
    const float* pos  = (const float*)d_in[3];
    const int*   bid  = (const int*)d_in[4];
    const float* ipw  = (const float*)d_in[5];
    const float* ipb  = (const float*)d_in[6];
    const float* opw  = (const float*)d_in[7];
    const float* opb  = (const float*)d_in[8];
    const float* l1w  = (const float*)d_in[9];
    const float* l1b  = (const float*)d_in[10];
    const float* l2w  = (const float*)d_in[11];
    const float* l2b  = (const float*)d_in[12];
    const float* n1w  = (const float*)d_in[13];
    const float* n1b  = (const float*)d_in[14];
    const float* n2w  = (const float*)d_in[15];
    const float* n2b  = (const float*)d_in[16];
    const float* n3w  = (const float*)d_in[17];
    const float* n3b  = (const float*)d_in[18];

    float* out = (float*)d_out;

    __nv_bfloat16 *qk16, *qin16, *feat16, *v16, *x16, *h16, *w16;
    float *x32;
    cudaGetSymbolAddress((void**)&qk16, g_qk16);
    cudaGetSymbolAddress((void**)&qin16, g_qin16);
    cudaGetSymbolAddress((void**)&feat16, g_feat16);
    cudaGetSymbolAddress((void**)&v16, g_v16);
    cudaGetSymbolAddress((void**)&x16, g_x16);
    cudaGetSymbolAddress((void**)&h16, g_h16);
    cudaGetSymbolAddress((void**)&w16, g_w16);
    cudaGetSymbolAddress((void**)&x32, g_x32);

    cudaFuncSetAttribute((const void*)gemm_bf16_kernel<__nv_bfloat16, true>,
                         cudaFuncAttributeMaxDynamicSharedMemorySize, GEMM_SMEM);
    cudaFuncSetAttribute((const void*)qkv_gemm_kernel,
                         cudaFuncAttributeMaxDynamicSharedMemorySize, GEMM_SMEM);
    cudaFuncSetAttribute((const void*)gemm_op_ln1_kernel,
                         cudaFuncAttributeMaxDynamicSharedMemorySize, FUSED_SMEM);
    cudaFuncSetAttribute((const void*)gemm_ffn_ln23_kernel,
                         cudaFuncAttributeMaxDynamicSharedMemorySize, FUSED_SMEM);
    cudaFuncSetAttribute((const void*)attn_kernel,
                         cudaFuncAttributeMaxDynamicSharedMemorySize, ATTN_SMEM);

    cvt_all_kernel<<<(W16_TOT / 4 + 255) / 256, 256>>>(ipw, opw, l1w, l2w, w16);

    const int TOT4 = NVOX * (CDIM / 4);
    dim3 pgrid((TOT4 + 255) / 256);
    dim3 gridQKV(9, NVOX / 256);
    dim3 grid768(DFF / 64, NVOX / 256);
    dim3 fgrid(NVOX / 64);

    for (int i = 0; i < 2; i++) {
        const __nv_bfloat16* Wqkv = w16 + IPW_OFF + (size_t)i * 3 * CDIM * CDIM;
        const float* bqkv = ipb + (size_t)i * 3 * CDIM;
        const float* cur = (i == 0) ? src : out;

        // 1. prep: only for layer 0 (layer 1's prep is fused into ffn_ln23 below)
        if (i == 0) {
            prep_kernel<<<pgrid, 256>>>(cur, pos, qin16, feat16);
        }

        // 2. merged QKV projection (voxel order)
        qkv_gemm_kernel<<<gridQKV, 256, GEMM_SMEM>>>(
            qin16, feat16, Wqkv, bqkv, qk16, v16);

        // 3. attention (indirect gather) -> qin16 (set order)
        attn_kernel<<<NSET, 288, ATTN_SMEM>>>(qk16, v16, inds, bid, i, qin16);

        // 4. fused out_proj + scatter + residual + LN1 -> x32, x16
        gemm_op_ln1_kernel<<<fgrid, 256, FUSED_SMEM>>>(
            qin16, w16 + OPW_OFF + (size_t)i * CDIM * CDIM, opb + (size_t)i * CDIM,
            cur, inds, bid, i, n1w + i * CDIM, n1b + i * CDIM, x32, x16);

        // 5. FFN lin1 + relu -> h16
        gemm_bf16_kernel<__nv_bfloat16, true><<<grid768, 256, GEMM_SMEM>>>(
            x16, w16 + L1W_OFF + (size_t)i * DFF * CDIM, l1b + (size_t)i * DFF,
            h16, CDIM, DFF);

        // 6. fused lin2 + LN2 + LN3 -> out; on layer 0 also emit next layer's
        //    prep (qin16 = bf16(out + pos[1]), feat16 = bf16(out))
        const float* posN = (i == 0) ? (pos + (size_t)NVOX * CDIM) : nullptr;
        gemm_ffn_ln23_kernel<<<fgrid, 256, FUSED_SMEM>>>(
            h16, w16 + L2W_OFF + (size_t)i * CDIM * DFF, l2b + (size_t)i * CDIM,
            x32, cur, n2w + i * CDIM, n2b + i * CDIM,
            n3w + i * CDIM, n3b + i * CDIM, out,
            posN, (i == 0) ? qin16 : nullptr, (i == 0) ? feat16 : nullptr);
    }
}

// round 15
// speedup vs baseline: 1.0815x; 1.0064x over previous
#include <cuda_runtime.h>
#include <cuda_bf16.h>
#include <math.h>
#include <stdint.h>

// Problem constants
#define NVOX 147456
#define CDIM 192
#define NH 8
#define DH 24
#define DFF 768
#define SETSZ 36
#define NSET 4096

// ---------------------------------------------------------------------------
// Scratch (device globals)
// ---------------------------------------------------------------------------
__device__ __nv_bfloat16 g_qk16[(size_t)NVOX * 2 * CDIM];  // Q|K voxel-order (stride 384)
__device__ __nv_bfloat16 g_qin16[(size_t)NVOX * CDIM];     // q_in (voxel) / attn out (set)
__device__ __nv_bfloat16 g_feat16[(size_t)NVOX * CDIM];    // bf16(cur), voxel order
__device__ __nv_bfloat16 g_v16[(size_t)NVOX * CDIM];       // V, voxel order
__device__ __nv_bfloat16 g_x16[(size_t)NVOX * CDIM];
__device__ __nv_bfloat16 g_h16[(size_t)NVOX * DFF];
__device__ float g_x32[(size_t)NVOX * CDIM];   // post-LN1 x (fp32)
// bf16 weights: [ipw | opw | l1w | l2w]
#define IPW_OFF 0
#define OPW_OFF 221184
#define L1W_OFF 294912
#define L2W_OFF 589824
#define W16_TOT 884736
__device__ __nv_bfloat16 g_w16[W16_TOT];

// ---------------------------------------------------------------------------
// mma.sync helpers
// ---------------------------------------------------------------------------
__device__ __forceinline__ void cp16(uint32_t dst, const void* src) {
    asm volatile("cp.async.cg.shared.global [%0], [%1], 16;\n" :: "r"(dst), "l"(src));
}
__device__ __forceinline__ void ldsm4(uint32_t* r, uint32_t addr) {
    asm volatile("ldmatrix.sync.aligned.m8n8.x4.shared.b16 {%0,%1,%2,%3}, [%4];"
                 : "=r"(r[0]), "=r"(r[1]), "=r"(r[2]), "=r"(r[3]) : "r"(addr));
}
__device__ __forceinline__ void mma_bf16(float* c, const uint32_t* a, const uint32_t* b) {
    asm volatile(
        "mma.sync.aligned.m16n8k16.row.col.f32.bf16.bf16.f32 "
        "{%0,%1,%2,%3},{%4,%5,%6,%7},{%8,%9},{%0,%1,%2,%3};"
        : "+f"(c[0]), "+f"(c[1]), "+f"(c[2]), "+f"(c[3])
        : "r"(a[0]), "r"(a[1]), "r"(a[2]), "r"(a[3]), "r"(b[0]), "r"(b[1]));
}
// Last chunk waits for its OWN group (wait_group 0); earlier leave prefetch in flight.
__device__ __forceinline__ void cp_wait(bool last) {
    if (last) asm volatile("cp.async.wait_group 0;" ::: "memory");
    else      asm volatile("cp.async.wait_group 1;" ::: "memory");
}
// Unpack 8 bf16 (uint4) -> two float4
__device__ __forceinline__ void unpack8_f4(uint4 u, float4& lo, float4& hi) {
    uint32_t w[4] = {u.x, u.y, u.z, u.w};
    float2 t0 = __bfloat1622float2(*reinterpret_cast<__nv_bfloat162*>(&w[0]));
    float2 t1 = __bfloat1622float2(*reinterpret_cast<__nv_bfloat162*>(&w[1]));
    float2 t2 = __bfloat1622float2(*reinterpret_cast<__nv_bfloat162*>(&w[2]));
    float2 t3 = __bfloat1622float2(*reinterpret_cast<__nv_bfloat162*>(&w[3]));
    lo = make_float4(t0.x, t0.y, t1.x, t1.y);
    hi = make_float4(t2.x, t2.y, t3.x, t3.y);
}
// Packed f32x2 helpers (Blackwell FFMA2 path)
__device__ __forceinline__ void ffma2(uint64_t& d, uint64_t a, uint64_t b) {
    asm("fma.rn.f32x2 %0, %1, %2, %0;" : "+l"(d) : "l"(a), "l"(b));
}
__device__ __forceinline__ uint64_t pack2(float lo, float hi) {
    uint64_t r;
    asm("mov.b64 %0, {%1, %2};" : "=l"(r) : "f"(lo), "f"(hi));
    return r;
}
__device__ __forceinline__ float2 unpack2(uint64_t v) {
    float2 r;
    asm("mov.b64 {%0, %1}, %2;" : "=f"(r.x), "=f"(r.y) : "l"(v));
    return r;
}

// ---------------------------------------------------------------------------
// Plain GEMM mainloop body (tile 256x64x32, 8 warps 4m x 2n, 3-stage).
// ---------------------------------------------------------------------------
#define GA_STAGE 16384
#define GB_STAGE 4096
#define GB_BASE  (3 * GA_STAGE)
#define GEMM_SMEM (3 * GA_STAGE + 3 * GB_STAGE)  // 61440

#define PLAIN_MAINLOOP(Aptr, Wptr, Kval)                                          \
    float acc[4][4][4];                                                           \
    _Pragma("unroll")                                                             \
    for (int mt = 0; mt < 4; mt++)                                                \
        _Pragma("unroll")                                                         \
        for (int nt = 0; nt < 4; nt++)                                            \
            _Pragma("unroll")                                                     \
            for (int r = 0; r < 4; r++) acc[mt][nt][r] = 0.f;                     \
    auto stage = [&](int kt, int buf) {                                           \
        const int k0 = kt * 32;                                                   \
        const uint32_t aB = sbase + buf * GA_STAGE;                               \
        const uint32_t bB = sbase + GB_BASE + buf * GB_STAGE;                     \
        _Pragma("unroll")                                                         \
        for (int i = 0; i < 4; i++) {                                             \
            int idx = i * 256 + tid;                                              \
            int row = idx >> 2, ch = idx & 3;                                     \
            cp16(aB + row * 64 + ((ch ^ ((row >> 1) & 3)) * 16),                  \
                 (Aptr) + (size_t)(m0 + row) * (Kval) + k0 + ch * 8);             \
        }                                                                         \
        {                                                                         \
            int row = tid >> 2, ch = tid & 3;                                     \
            cp16(bB + row * 64 + ((ch ^ ((row >> 1) & 3)) * 16),                  \
                 (Wptr) + (size_t)(n0 + row) * (Kval) + k0 + ch * 8);             \
        }                                                                         \
        asm volatile("cp.async.commit_group;" ::: "memory");                      \
    };                                                                            \
    const int nk = (Kval) >> 5;                                                   \
    stage(0, 0);                                                                  \
    stage(1, 1);                                                                  \
    for (int t = 0; t < nk; t++) {                                                \
        const int buf = t % 3;                                                    \
        cp_wait(t == nk - 1);                                                     \
        __syncthreads();                                                          \
        const uint32_t aB = sbase + buf * GA_STAGE;                               \
        const uint32_t bB = sbase + GB_BASE + buf * GB_STAGE;                     \
        _Pragma("unroll")                                                         \
        for (int ks = 0; ks < 2; ks++) {                                          \
            uint32_t af[4][4], bf[4][2];                                          \
            _Pragma("unroll")                                                     \
            for (int mt = 0; mt < 4; mt++) {                                      \
                int row = wm + mt * 16 + (lane & 15);                             \
                int ch = ks * 2 + (lane >> 4);                                    \
                ldsm4(af[mt], aB + row * 64 + ((ch ^ ((row >> 1) & 3)) * 16));    \
            }                                                                     \
            _Pragma("unroll")                                                     \
            for (int p = 0; p < 2; p++) {                                         \
                int row = wn + p * 16 + ((lane >> 4) << 3) + (lane & 7);          \
                int ch = ks * 2 + ((lane >> 3) & 1);                              \
                uint32_t r4[4];                                                   \
                ldsm4(r4, bB + row * 64 + ((ch ^ ((row >> 1) & 3)) * 16));        \
                bf[p * 2 + 0][0] = r4[0]; bf[p * 2 + 0][1] = r4[1];               \
                bf[p * 2 + 1][0] = r4[2]; bf[p * 2 + 1][1] = r4[3];               \
            }                                                                     \
            _Pragma("unroll")                                                     \
            for (int mt = 0; mt < 4; mt++)                                        \
                _Pragma("unroll")                                                 \
                for (int nt = 0; nt < 4; nt++)                                    \
                    mma_bf16(acc[mt][nt], af[mt], bf[nt]);                        \
        }                                                                         \
        __syncthreads();                                                          \
        if (t + 2 < nk) stage(t + 2, (t + 2) % 3);                                \
    }

// ---------------------------------------------------------------------------
// Plain bf16 GEMM (lin1): D[M,Nc] = A @ W^T + bias (opt ReLU)
// ---------------------------------------------------------------------------
template <typename OutT, bool RELU>
__global__ __launch_bounds__(256) void gemm_bf16_kernel(
        const __nv_bfloat16* __restrict__ A,
        const __nv_bfloat16* __restrict__ W,
        const float* __restrict__ bias,
        OutT* __restrict__ D,
        int K, int Nc) {
    extern __shared__ unsigned char smem[];
    const uint32_t sbase = (uint32_t)__cvta_generic_to_shared(smem);
    const int tid = threadIdx.x;
    const int lane = tid & 31;
    const int wid = tid >> 5;
    const int wm = (wid & 3) * 64;
    const int wn = (wid >> 2) * 32;
    const int m0 = blockIdx.y * 256;
    const int n0 = blockIdx.x * 64;

    PLAIN_MAINLOOP(A, W, K)

#pragma unroll
    for (int mt = 0; mt < 4; mt++) {
#pragma unroll
        for (int nt = 0; nt < 4; nt++) {
            int m = m0 + wm + mt * 16 + (lane >> 2);
            int n = n0 + wn + nt * 8 + (lane & 3) * 2;
            float b0 = bias[n], b1 = bias[n + 1];
            float v0 = acc[mt][nt][0] + b0;
            float v1 = acc[mt][nt][1] + b1;
            float v2 = acc[mt][nt][2] + b0;
            float v3 = acc[mt][nt][3] + b1;
            if (RELU) {
                v0 = fmaxf(v0, 0.f); v1 = fmaxf(v1, 0.f);
                v2 = fmaxf(v2, 0.f); v3 = fmaxf(v3, 0.f);
            }
            if constexpr (sizeof(OutT) == 2) {
                *reinterpret_cast<__nv_bfloat162*>((__nv_bfloat16*)D + (size_t)m * Nc + n) =
                    __floats2bfloat162_rn(v0, v1);
                *reinterpret_cast<__nv_bfloat162*>((__nv_bfloat16*)D + (size_t)(m + 8) * Nc + n) =
                    __floats2bfloat162_rn(v2, v3);
            } else {
                *reinterpret_cast<float2*>((float*)D + (size_t)m * Nc + n) = make_float2(v0, v1);
                *reinterpret_cast<float2*>((float*)D + (size_t)(m + 8) * Nc + n) = make_float2(v2, v3);
            }
        }
    }
}

// ---------------------------------------------------------------------------
// Merged QKV GEMM: Nc spans 576 (Wq|Wk|Wv rows contiguous).
// ---------------------------------------------------------------------------
__global__ __launch_bounds__(256) void qkv_gemm_kernel(
        const __nv_bfloat16* __restrict__ Aq,
        const __nv_bfloat16* __restrict__ Af,
        const __nv_bfloat16* __restrict__ W,
        const float* __restrict__ bias,
        __nv_bfloat16* __restrict__ Dqk,
        __nv_bfloat16* __restrict__ Dv) {
    extern __shared__ unsigned char smem[];
    const uint32_t sbase = (uint32_t)__cvta_generic_to_shared(smem);
    const int tid = threadIdx.x;
    const int lane = tid & 31;
    const int wid = tid >> 5;
    const int wm = (wid & 3) * 64;
    const int wn = (wid >> 2) * 32;
    const int m0 = blockIdx.y * 256;
    const int n0 = blockIdx.x * 64;

    const bool isV = (n0 >= 2 * CDIM);
    const __nv_bfloat16* A = isV ? Af : Aq;
    __nv_bfloat16* D = isV ? Dv : Dqk;
    const int dStride = isV ? CDIM : 2 * CDIM;
    const int dCol0 = isV ? n0 - 2 * CDIM : n0;

    PLAIN_MAINLOOP(A, W, CDIM)

#pragma unroll
    for (int mt = 0; mt < 4; mt++) {
#pragma unroll
        for (int nt = 0; nt < 4; nt++) {
            int m = m0 + wm + mt * 16 + (lane >> 2);
            int nl = wn + nt * 8 + (lane & 3) * 2;
            int n = n0 + nl;
            float b0 = bias[n], b1 = bias[n + 1];
            int nd = dCol0 + nl;
            *reinterpret_cast<__nv_bfloat162*>(D + (size_t)m * dStride + nd) =
                __floats2bfloat162_rn(acc[mt][nt][0] + b0, acc[mt][nt][1] + b1);
            *reinterpret_cast<__nv_bfloat162*>(D + (size_t)(m + 8) * dStride + nd) =
                __floats2bfloat162_rn(acc[mt][nt][2] + b0, acc[mt][nt][3] + b1);
        }
    }
}

// ---------------------------------------------------------------------------
// Fused GEMM mainloop config (tile 64 x 192, K chunks of 32, 3-stage).
// ---------------------------------------------------------------------------
#define FA_STAGE 4096
#define FB_STAGE 12288
#define FB_BASE  (3 * FA_STAGE)
#define FUSED_SMEM (3 * FA_STAGE + 3 * FB_STAGE)  // 49152

#define FUSED_MAINLOOP(Aptr, Wptr, Kval)                                              \
    float acc[2][6][4];                                                               \
    _Pragma("unroll")                                                                 \
    for (int mt = 0; mt < 2; mt++)                                                    \
        _Pragma("unroll")                                                             \
        for (int nt = 0; nt < 6; nt++)                                                \
            _Pragma("unroll")                                                         \
            for (int r = 0; r < 4; r++) acc[mt][nt][r] = 0.f;                         \
    auto stage = [&](int kt, int buf) {                                               \
        const int k0 = kt * 32;                                                       \
        {                                                                             \
            int row = tid >> 2, ch = tid & 3;                                         \
            cp16(sbase + buf * FA_STAGE + row * 64 + ((ch ^ ((row >> 1) & 3)) * 16),  \
                 (Aptr) + (size_t)(m0 + row) * (Kval) + k0 + ch * 8);                 \
        }                                                                             \
        _Pragma("unroll")                                                             \
        for (int i = 0; i < 3; i++) {                                                 \
            int idx = i * 256 + tid;                                                  \
            int row = idx >> 2, ch = idx & 3;                                         \
            cp16(sbase + FB_BASE + buf * FB_STAGE + row * 64 +                        \
                     ((ch ^ ((row >> 1) & 3)) * 16),                                  \
                 (Wptr) + (size_t)row * (Kval) + k0 + ch * 8);                        \
        }                                                                             \
        asm volatile("cp.async.commit_group;" ::: "memory");                          \
    };                                                                                \
    const int nk = (Kval) >> 5;                                                       \
    stage(0, 0);                                                                      \
    stage(1, 1);                                                                      \
    for (int t = 0; t < nk; t++) {                                                    \
        const int buf = t % 3;                                                        \
        cp_wait(t == nk - 1);                                                         \
        __syncthreads();                                                              \
        const uint32_t aB = sbase + buf * FA_STAGE;                                   \
        const uint32_t bB = sbase + FB_BASE + buf * FB_STAGE;                         \
        _Pragma("unroll")                                                             \
        for (int ks = 0; ks < 2; ks++) {                                              \
            uint32_t af[2][4], bf[6][2];                                              \
            _Pragma("unroll")                                                         \
            for (int mt = 0; mt < 2; mt++) {                                          \
                int row = wm + mt * 16 + (lane & 15);                                 \
                int ch = ks * 2 + (lane >> 4);                                        \
                ldsm4(af[mt], aB + row * 64 + ((ch ^ ((row >> 1) & 3)) * 16));        \
            }                                                                         \
            _Pragma("unroll")                                                         \
            for (int p = 0; p < 3; p++) {                                             \
                int row = wn + p * 16 + ((lane >> 4) << 3) + (lane & 7);              \
                int ch = ks * 2 + ((lane >> 3) & 1);                                  \
                uint32_t r4[4];                                                       \
                ldsm4(r4, bB + row * 64 + ((ch ^ ((row >> 1) & 3)) * 16));            \
                bf[p * 2 + 0][0] = r4[0]; bf[p * 2 + 0][1] = r4[1];                   \
                bf[p * 2 + 1][0] = r4[2]; bf[p * 2 + 1][1] = r4[3];                   \
            }                                                                         \
            _Pragma("unroll")                                                         \
            for (int mt = 0; mt < 2; mt++)                                            \
                _Pragma("unroll")                                                     \
                for (int nt = 0; nt < 6; nt++)                                        \
                    mma_bf16(acc[mt][nt], af[mt], bf[nt]);                            \
        }                                                                             \
        __syncthreads();                                                              \
        if (t + 2 < nk) stage(t + 2, (t + 2) % 3);                                    \
    }

// ---------------------------------------------------------------------------
// Fused out_proj + scatter + residual + LN1.
// ---------------------------------------------------------------------------
__global__ __launch_bounds__(256) void gemm_op_ln1_kernel(
        const __nv_bfloat16* __restrict__ A,
        const __nv_bfloat16* __restrict__ W,
        const float* __restrict__ bias,
        const float* __restrict__ cur,
        const int* __restrict__ inds_all, const int* __restrict__ block_id, int layer,
        const float* __restrict__ lnw, const float* __restrict__ lnb,
        float* __restrict__ x32, __nv_bfloat16* __restrict__ x16) {
    extern __shared__ unsigned char smem[];
    const uint32_t sbase = (uint32_t)__cvta_generic_to_shared(smem);
    const int tid = threadIdx.x;
    const int lane = tid & 31;
    const int wid = tid >> 5;
    const int wm = (wid & 1) * 32;
    const int wn = (wid >> 1) * 48;
    const int m0 = blockIdx.x * 64;

    FUSED_MAINLOOP(A, W, CDIM)

    float* stats = reinterpret_cast<float*>(smem);
    const int gid = lane >> 2, tig = lane & 3;
    const int shift = block_id[0] & 1;
    const int* ip = inds_all + ((size_t)shift * 2 + layer) * NVOX;
    int vrow[2][2];
#pragma unroll
    for (int mt = 0; mt < 2; mt++) {
#pragma unroll
        for (int mm = 0; mm < 2; mm++) {
            int rloc = wm + mt * 16 + mm * 8 + gid;
            int v = ip[m0 + rloc];
            vrow[mt][mm] = v;
            float s = 0.f, s2 = 0.f;
#pragma unroll
            for (int nt = 0; nt < 6; nt++) {
                int n = wn + nt * 8 + tig * 2;
                float2 c = *reinterpret_cast<const float2*>(cur + (size_t)v * CDIM + n);
                float a0 = acc[mt][nt][mm * 2]     + bias[n]     + c.x;
                float a1 = acc[mt][nt][mm * 2 + 1] + bias[n + 1] + c.y;
                acc[mt][nt][mm * 2] = a0; acc[mt][nt][mm * 2 + 1] = a1;
                s += a0 + a1; s2 += a0 * a0 + a1 * a1;
            }
            s  += __shfl_xor_sync(0xffffffffu, s, 1);  s  += __shfl_xor_sync(0xffffffffu, s, 2);
            s2 += __shfl_xor_sync(0xffffffffu, s2, 1); s2 += __shfl_xor_sync(0xffffffffu, s2, 2);
            if (tig == 0) {
                stats[((wid >> 1) * 64 + rloc) * 2]     = s;
                stats[((wid >> 1) * 64 + rloc) * 2 + 1] = s2;
            }
        }
    }
    __syncthreads();
#pragma unroll
    for (int mt = 0; mt < 2; mt++) {
#pragma unroll
        for (int mm = 0; mm < 2; mm++) {
            int rloc = wm + mt * 16 + mm * 8 + gid;
            int v = vrow[mt][mm];
            float S = 0.f, S2 = 0.f;
#pragma unroll
            for (int g = 0; g < 4; g++) {
                S  += stats[(g * 64 + rloc) * 2];
                S2 += stats[(g * 64 + rloc) * 2 + 1];
            }
            float mean = S * (1.0f / CDIM);
            float var = S2 * (1.0f / CDIM) - mean * mean;
            float rs = rsqrtf(var + 1e-5f);
#pragma unroll
            for (int nt = 0; nt < 6; nt++) {
                int n = wn + nt * 8 + tig * 2;
                float o0 = (acc[mt][nt][mm * 2]     - mean) * rs * lnw[n]     + lnb[n];
                float o1 = (acc[mt][nt][mm * 2 + 1] - mean) * rs * lnw[n + 1] + lnb[n + 1];
                *reinterpret_cast<float2*>(x32 + (size_t)v * CDIM + n) = make_float2(o0, o1);
                *reinterpret_cast<__nv_bfloat162*>(x16 + (size_t)v * CDIM + n) =
                    __floats2bfloat162_rn(o0, o1);
            }
        }
    }
}

// ---------------------------------------------------------------------------
// Fused lin2 + LN2 + LN3 (voxel-order rows). Optionally also emits next
// layer's prep outputs: qinN = bf16(out + posN), featN = bf16(out).
// ---------------------------------------------------------------------------
__global__ __launch_bounds__(256) void gemm_ffn_ln23_kernel(
        const __nv_bfloat16* __restrict__ A,
        const __nv_bfloat16* __restrict__ W,
        const float* __restrict__ bias,
        const float* __restrict__ x32,
        const float* __restrict__ cur,
        const float* __restrict__ w2, const float* __restrict__ b2,
        const float* __restrict__ w3, const float* __restrict__ b3,
        float* __restrict__ outp,
        const float* __restrict__ posN,
        __nv_bfloat16* __restrict__ qinN,
        __nv_bfloat16* __restrict__ featN) {
    extern __shared__ unsigned char smem[];
    const uint32_t sbase = (uint32_t)__cvta_generic_to_shared(smem);
    const int tid = threadIdx.x;
    const int lane = tid & 31;
    const int wid = tid >> 5;
    const int wm = (wid & 1) * 32;
    const int wn = (wid >> 1) * 48;
    const int m0 = blockIdx.x * 64;

    FUSED_MAINLOOP(A, W, DFF)

    float* stats = reinterpret_cast<float*>(smem);
    const int gid = lane >> 2, tig = lane & 3;

#pragma unroll
    for (int mt = 0; mt < 2; mt++) {
#pragma unroll
        for (int mm = 0; mm < 2; mm++) {
            int rloc = wm + mt * 16 + mm * 8 + gid;
            int v = m0 + rloc;
            float s = 0.f, s2 = 0.f;
#pragma unroll
            for (int nt = 0; nt < 6; nt++) {
                int n = wn + nt * 8 + tig * 2;
                float2 xr = *reinterpret_cast<const float2*>(x32 + (size_t)v * CDIM + n);
                float a0 = acc[mt][nt][mm * 2]     + bias[n]     + xr.x;
                float a1 = acc[mt][nt][mm * 2 + 1] + bias[n + 1] + xr.y;
                acc[mt][nt][mm * 2] = a0; acc[mt][nt][mm * 2 + 1] = a1;
                s += a0 + a1; s2 += a0 * a0 + a1 * a1;
            }
            s  += __shfl_xor_sync(0xffffffffu, s, 1);  s  += __shfl_xor_sync(0xffffffffu, s, 2);
            s2 += __shfl_xor_sync(0xffffffffu, s2, 1); s2 += __shfl_xor_sync(0xffffffffu, s2, 2);
            if (tig == 0) {
                stats[((wid >> 1) * 64 + rloc) * 2]     = s;
                stats[((wid >> 1) * 64 + rloc) * 2 + 1] = s2;
            }
        }
    }
    __syncthreads();

    float sB[2][2], s2B[2][2];
#pragma unroll
    for (int mt = 0; mt < 2; mt++) {
#pragma unroll
        for (int mm = 0; mm < 2; mm++) {
            int rloc = wm + mt * 16 + mm * 8 + gid;
            int v = m0 + rloc;
            float S = 0.f, S2 = 0.f;
#pragma unroll
            for (int g = 0; g < 4; g++) {
                S  += stats[(g * 64 + rloc) * 2];
                S2 += stats[(g * 64 + rloc) * 2 + 1];
            }
            float mean = S * (1.0f / CDIM);
            float var = S2 * (1.0f / CDIM) - mean * mean;
            float rs = rsqrtf(var + 1e-5f);
            float s = 0.f, s2 = 0.f;
#pragma unroll
            for (int nt = 0; nt < 6; nt++) {
                int n = wn + nt * 8 + tig * 2;
                float2 cv = *reinterpret_cast<const float2*>(cur + (size_t)v * CDIM + n);
                float t0 = (acc[mt][nt][mm * 2]     - mean) * rs * w2[n]     + b2[n]     + cv.x;
                float t1 = (acc[mt][nt][mm * 2 + 1] - mean) * rs * w2[n + 1] + b2[n + 1] + cv.y;
                acc[mt][nt][mm * 2] = t0; acc[mt][nt][mm * 2 + 1] = t1;
                s += t0 + t1; s2 += t0 * t0 + t1 * t1;
            }
            s  += __shfl_xor_sync(0xffffffffu, s, 1);  s  += __shfl_xor_sync(0xffffffffu, s, 2);
            s2 += __shfl_xor_sync(0xffffffffu, s2, 1); s2 += __shfl_xor_sync(0xffffffffu, s2, 2);
            sB[mt][mm] = s; s2B[mt][mm] = s2;
        }
    }
    __syncthreads();
#pragma unroll
    for (int mt = 0; mt < 2; mt++)
#pragma unroll
        for (int mm = 0; mm < 2; mm++) {
            int rloc = wm + mt * 16 + mm * 8 + gid;
            if (tig == 0) {
                stats[((wid >> 1) * 64 + rloc) * 2]     = sB[mt][mm];
                stats[((wid >> 1) * 64 + rloc) * 2 + 1] = s2B[mt][mm];
            }
        }
    __syncthreads();

#pragma unroll
    for (int mt = 0; mt < 2; mt++) {
#pragma unroll
        for (int mm = 0; mm < 2; mm++) {
            int rloc = wm + mt * 16 + mm * 8 + gid;
            int v = m0 + rloc;
            float S = 0.f, S2 = 0.f;
#pragma unroll
            for (int g = 0; g < 4; g++) {
                S  += stats[(g * 64 + rloc) * 2];
                S2 += stats[(g * 64 + rloc) * 2 + 1];
            }
            float mean = S * (1.0f / CDIM);
            float var = S2 * (1.0f / CDIM) - mean * mean;
            float rs = rsqrtf(var + 1e-5f);
#pragma unroll
            for (int nt = 0; nt < 6; nt++) {
                int n = wn + nt * 8 + tig * 2;
                float o0 = (acc[mt][nt][mm * 2]     - mean) * rs * w3[n]     + b3[n];
                float o1 = (acc[mt][nt][mm * 2 + 1] - mean) * rs * w3[n + 1] + b3[n + 1];
                *reinterpret_cast<float2*>(outp + (size_t)v * CDIM + n) = make_float2(o0, o1);
                if (qinN) {
                    float2 pp = *reinterpret_cast<const float2*>(posN + (size_t)v * CDIM + n);
                    *reinterpret_cast<__nv_bfloat162*>(featN + (size_t)v * CDIM + n) =
                        __floats2bfloat162_rn(o0, o1);
                    *reinterpret_cast<__nv_bfloat162*>(qinN + (size_t)v * CDIM + n) =
                        __floats2bfloat162_rn(o0 + pp.x, o1 + pp.y);
                }
            }
        }
    }
}

// ---------------------------------------------------------------------------
// Single merged weight converter
// ---------------------------------------------------------------------------
__global__ void cvt_all_kernel(const float* __restrict__ ipw,
                               const float* __restrict__ opw,
                               const float* __restrict__ l1w,
                               const float* __restrict__ l2w,
                               __nv_bfloat16* __restrict__ dst) {
    int i = blockIdx.x * blockDim.x + threadIdx.x;
    const int N4 = W16_TOT / 4;
    if (i >= N4) return;
    int e = i * 4;
    const float* src;
    int off;
    if (e < OPW_OFF)      { src = ipw; off = e - IPW_OFF; }
    else if (e < L1W_OFF) { src = opw; off = e - OPW_OFF; }
    else if (e < L2W_OFF) { src = l1w; off = e - L1W_OFF; }
    else                  { src = l2w; off = e - L2W_OFF; }
    float4 v = *reinterpret_cast<const float4*>(src + off);
    reinterpret_cast<__nv_bfloat162*>(dst)[i * 2 + 0] = __floats2bfloat162_rn(v.x, v.y);
    reinterpret_cast<__nv_bfloat162*>(dst)[i * 2 + 1] = __floats2bfloat162_rn(v.z, v.w);
}

// ---------------------------------------------------------------------------
// Prep (coalesced, voxel order): qin16 = bf16(cur+pos); feat16 = bf16(cur)
// ---------------------------------------------------------------------------
__global__ void prep_kernel(const float* __restrict__ cur,
                            const float* __restrict__ pos,
                            __nv_bfloat16* __restrict__ qin,
                            __nv_bfloat16* __restrict__ feat) {
    int gid = blockIdx.x * blockDim.x + threadIdx.x;
    const int TOT = NVOX * (CDIM / 4);
    if (gid >= TOT) return;
    float4 f = reinterpret_cast<const float4*>(cur)[gid];
    float4 pp = reinterpret_cast<const float4*>(pos)[gid];
    __nv_bfloat162* f2 = reinterpret_cast<__nv_bfloat162*>(feat);
    __nv_bfloat162* q2 = reinterpret_cast<__nv_bfloat162*>(qin);
    f2[gid * 2 + 0] = __floats2bfloat162_rn(f.x, f.y);
    f2[gid * 2 + 1] = __floats2bfloat162_rn(f.z, f.w);
    q2[gid * 2 + 0] = __floats2bfloat162_rn(f.x + pp.x, f.y + pp.y);
    q2[gid * 2 + 1] = __floats2bfloat162_rn(f.z + pp.z, f.w + pp.w);
}

// ---------------------------------------------------------------------------
// Attention: one block per set, 288 threads = (36 rows x 8 heads).
// K and V staged fp32 in smem (unpacked once at fill); Q per-thread from
// global. All dot/accumulate math uses packed f32x2 (SASS FFMA2): halves
// the FMA instruction count at full fp32 precision.
// ---------------------------------------------------------------------------
#define ATTN_SMEM (2 * SETSZ * CDIM * 4 + 160)

__global__ __launch_bounds__(288) void attn_kernel(const __nv_bfloat16* __restrict__ qk,
                                                   const __nv_bfloat16* __restrict__ v,
                                                   const int* __restrict__ inds_all,
                                                   const int* __restrict__ block_id,
                                                   int layer,
                                                   __nv_bfloat16* __restrict__ o) {
    extern __shared__ float smf[];
    float* ks = smf;                      // 36 x 192 fp32
    float* vs = smf + SETSZ * CDIM;       // 36 x 192 fp32
    int* vids = reinterpret_cast<int*>(smf + 2 * SETSZ * CDIM);

    int s = blockIdx.x;
    int tid = threadIdx.x;

    if (tid < SETSZ) {
        int shift = block_id[0] & 1;
        vids[tid] = inds_all[((size_t)shift * 2 + layer) * NVOX + s * SETSZ + tid];
    }
    __syncthreads();

    const uint4* qk4 = reinterpret_cast<const uint4*>(qk);
    const uint4* v4 = reinterpret_cast<const uint4*>(v);

    // Fill K (qk row chunks 24..47) and V, unpack to fp32 once
    for (int idx = tid; idx < SETSZ * 24; idx += 288) {
        int row = idx / 24, c = idx % 24;
        uint4 u = qk4[(size_t)vids[row] * 48 + 24 + c];
        float4 lo, hi;
        unpack8_f4(u, lo, hi);
        float* dst = ks + row * CDIM + c * 8;
        reinterpret_cast<float4*>(dst)[0] = lo;
        reinterpret_cast<float4*>(dst)[1] = hi;
    }
    for (int idx = tid; idx < SETSZ * 24; idx += 288) {
        int row = idx / 24, c = idx % 24;
        uint4 u = v4[(size_t)vids[row] * 24 + c];
        float4 lo, hi;
        unpack8_f4(u, lo, hi);
        float* dst = vs + row * CDIM + c * 8;
        reinterpret_cast<float4*>(dst)[0] = lo;
        reinterpret_cast<float4*>(dst)[1] = hi;
    }

    int l = tid % SETSZ;
    int h = tid / SETSZ;

    // Per-thread Q row straight from global, pre-scaled, packed f32x2
    const float scale = 0.20412414523193154f;
    uint64_t qp[12];
    {
        const uint4* qrow = qk4 + (size_t)vids[l] * 48 + h * 3;
#pragma unroll
        for (int c = 0; c < 3; c++) {
            float4 lo, hi;
            unpack8_f4(qrow[c], lo, hi);
            qp[c * 4 + 0] = pack2(lo.x * scale, lo.y * scale);
            qp[c * 4 + 1] = pack2(lo.z * scale, lo.w * scale);
            qp[c * 4 + 2] = pack2(hi.x * scale, hi.y * scale);
            qp[c * 4 + 3] = pack2(hi.z * scale, hi.w * scale);
        }
    }
    __syncthreads();

    float sc[SETSZ];
    float mx = -1e30f;
#pragma unroll 4
    for (int m = 0; m < SETSZ; m++) {
        const ulonglong2* krow = reinterpret_cast<const ulonglong2*>(ks + m * CDIM + h * DH);
        uint64_t d0 = 0, d1 = 0;   // packed (0,0)
#pragma unroll
        for (int c = 0; c < 6; c++) {
            ulonglong2 t = krow[c];
            ffma2(d0, qp[c * 2 + 0], t.x);
            ffma2(d1, qp[c * 2 + 1], t.y);
        }
        float2 a = unpack2(d0), b = unpack2(d1);
        float dot = (a.x + a.y) + (b.x + b.y);
        sc[m] = dot;
        mx = fmaxf(mx, dot);
    }
    float sum = 0.f;
#pragma unroll 4
    for (int m = 0; m < SETSZ; m++) {
        sc[m] = __expf(sc[m] - mx);
        sum += sc[m];
    }
    float inv = 1.0f / sum;

    // attn @ V with packed accumulators (12 x f32x2 = 24 lanes)
    uint64_t acc2[12];
#pragma unroll
    for (int j = 0; j < 12; j++) acc2[j] = 0;
#pragma unroll 4
    for (int m = 0; m < SETSZ; m++) {
        const ulonglong2* vrow = reinterpret_cast<const ulonglong2*>(vs + m * CDIM + h * DH);
        uint64_t p2 = pack2(sc[m], sc[m]);
#pragma unroll
        for (int c = 0; c < 6; c++) {
            ulonglong2 t = vrow[c];
            ffma2(acc2[c * 2 + 0], p2, t.x);
            ffma2(acc2[c * 2 + 1], p2, t.y);
        }
    }

    __nv_bfloat162* o2 = reinterpret_cast<__nv_bfloat162*>(
        o + (size_t)s * SETSZ * CDIM + l * CDIM + h * DH);
#pragma unroll
    for (int j = 0; j < 12; j++) {
        float2 t = unpack2(acc2[j]);
        o2[j] = __floats2bfloat162_rn(t.x * inv, t.y * inv);
    }
}

// ---------------------------------------------------------------------------
// Host orchestration
// ---------------------------------------------------------------------------
extern "C" void kernel_launch(void* const* d_in, const int* in_sizes, int n_in,
                              void* d_out, int out_size) {
    (void)in_sizes; (void)n_in; (void)out_size;
    const float* src  = (const float*)d_in[0];
    const int*   inds = (const int*)d_in[1];
    const float* pos  = (const float*)d_in[3];
    const int*   bid  = (const int*)d_in[4];
    const float* ipw  = (const float*)d_in[5];
    const float* ipb  = (const float*)d_in[6];
    const float* opw  = (const float*)d_in[7];
    const float* opb  = (const float*)d_in[8];
    const float* l1w  = (const float*)d_in[9];
    const float* l1b  = (const float*)d_in[10];
    const float* l2w  = (const float*)d_in[11];
    const float* l2b  = (const float*)d_in[12];
    const float* n1w  = (const float*)d_in[13];
    const float* n1b  = (const float*)d_in[14];
    const float* n2w  = (const float*)d_in[15];
    const float* n2b  = (const float*)d_in[16];
    const float* n3w  = (const float*)d_in[17];
    const float* n3b  = (const float*)d_in[18];

    float* out = (float*)d_out;

    __nv_bfloat16 *qk16, *qin16, *feat16, *v16, *x16, *h16, *w16;
    float *x32;
    cudaGetSymbolAddress((void**)&qk16, g_qk16);
    cudaGetSymbolAddress((void**)&qin16, g_qin16);
    cudaGetSymbolAddress((void**)&feat16, g_feat16);
    cudaGetSymbolAddress((void**)&v16, g_v16);
    cudaGetSymbolAddress((void**)&x16, g_x16);
    cudaGetSymbolAddress((void**)&h16, g_h16);
    cudaGetSymbolAddress((void**)&w16, g_w16);
    cudaGetSymbolAddress((void**)&x32, g_x32);

    cudaFuncSetAttribute((const void*)gemm_bf16_kernel<__nv_bfloat16, true>,
                         cudaFuncAttributeMaxDynamicSharedMemorySize, GEMM_SMEM);
    cudaFuncSetAttribute((const void*)qkv_gemm_kernel,
                         cudaFuncAttributeMaxDynamicSharedMemorySize, GEMM_SMEM);
    cudaFuncSetAttribute((const void*)gemm_op_ln1_kernel,
                         cudaFuncAttributeMaxDynamicSharedMemorySize, FUSED_SMEM);
    cudaFuncSetAttribute((const void*)gemm_ffn_ln23_kernel,
                         cudaFuncAttributeMaxDynamicSharedMemorySize, FUSED_SMEM);
    cudaFuncSetAttribute((const void*)attn_kernel,
                         cudaFuncAttributeMaxDynamicSharedMemorySize, ATTN_SMEM);

    cvt_all_kernel<<<(W16_TOT / 4 + 255) / 256, 256>>>(ipw, opw, l1w, l2w, w16);

    const int TOT4 = NVOX * (CDIM / 4);
    dim3 pgrid((TOT4 + 255) / 256);
    dim3 gridQKV(9, NVOX / 256);
    dim3 grid768(DFF / 64, NVOX / 256);
    dim3 fgrid(NVOX / 64);

    for (int i = 0; i < 2; i++) {
        const __nv_bfloat16* Wqkv = w16 + IPW_OFF + (size_t)i * 3 * CDIM * CDIM;
        const float* bqkv = ipb + (size_t)i * 3 * CDIM;
        const float* cur = (i == 0) ? src : out;

        if (i == 0) {
            prep_kernel<<<pgrid, 256>>>(cur, pos, qin16, feat16);
        }

        qkv_gemm_kernel<<<gridQKV, 256, GEMM_SMEM>>>(
            qin16, feat16, Wqkv, bqkv, qk16, v16);

        attn_kernel<<<NSET, 288, ATTN_SMEM>>>(qk16, v16, inds, bid, i, qin16);

        gemm_op_ln1_kernel<<<fgrid, 256, FUSED_SMEM>>>(
            qin16, w16 + OPW_OFF + (size_t)i * CDIM * CDIM, opb + (size_t)i * CDIM,
            cur, inds, bid, i, n1w + i * CDIM, n1b + i * CDIM, x32, x16);

        gemm_bf16_kernel<__nv_bfloat16, true><<<grid768, 256, GEMM_SMEM>>>(
            x16, w16 + L1W_OFF + (size_t)i * DFF * CDIM, l1b + (size_t)i * DFF,
            h16, CDIM, DFF);

        const float* posN = (i == 0) ? (pos + (size_t)NVOX * CDIM) : nullptr;
        gemm_ffn_ln23_kernel<<<fgrid, 256, FUSED_SMEM>>>(
            h16, w16 + L2W_OFF + (size_t)i * CDIM * DFF, l2b + (size_t)i * CDIM,
            x32, cur, n2w + i * CDIM, n2b + i * CDIM,
            n3w + i * CDIM, n3b + i * CDIM, out,
            posN, (i == 0) ? qin16 : nullptr, (i == 0) ? feat16 : nullptr);
    }
}